// round 13
// baseline (speedup 1.0000x reference)
#include <cuda_runtime.h>
#include <cuda_bf16.h>
#include <math.h>
#include <stdint.h>

#define BB 8
#define NN 512
#define KK 32
#define DD 128
#define HH 128
#define PP 8
#define NODES (BB*NN)

// Scratch (allocation-free rule: __device__ globals)
__device__ float g_pg[NODES*PP*3];
__device__ float g_R[NODES*9];
__device__ float g_t[NODES*3];
__device__ float g_s1[NODES*HH];        // static layer-1 pre-activation (incl bias)
__device__ float g_hs[NODES*HH];        // post-LN1 hidden state
__device__ uint32_t g_sA[NODES*80];     // bf16-packed static A rows: hv(64)|pl(12)|pln(4) u32

// fragment-packed bf16 weights: [ng][ks][nth][lane] -> uint4(b0a,b1a,b0b,b1b)
__device__ uint4 g_w1e_b[2*16*4*32];   // Wm1 rows 128..383 (K=256, KS=16)
__device__ uint4 g_w1g_b[2*3*4*32];    // Wm1 rows 416..455 (K=40->48, KS=3)
__device__ uint4 g_ws_b[2*10*4*32];    // Wm1 static rows (K=160, KS=10; row map k<128?k:k+256)
__device__ uint4 g_w2_b[2*8*4*32];     // Wm2 (K=128, KS=8)
__device__ uint4 g_w3_b[2*8*4*32];     // Wm3
__device__ uint4 g_wd1_b[8*8*4*32];    // Wd1 (K=128, N=512: 8 n-groups, KS=8)
__device__ uint4 g_wd2_b[2*32*4*32];   // Wd2 (K=512, N=128: KS=32)

__device__ __forceinline__ uint32_t pkbf(float a, float b) {
    __nv_bfloat162 h = __floats2bfloat162_rn(a, b);
    return *reinterpret_cast<uint32_t*>(&h);
}

// ---------------------------------------------------------------------------
// weight packing helper (bf16 mma-fragment order)
// ---------------------------------------------------------------------------
__device__ __forceinline__ uint4 packb(const float* __restrict__ W, int ld,
                                       int Krows, int i, int KS)
{
    int lane = i & 31;
    int nth  = (i >> 5) & 3;
    int rest = i >> 7;
    int ks = rest % KS;
    int ng = rest / KS;
    int q = lane & 3;
    int gid = lane >> 2;
    int k0 = ks * 16;
    int na = ng*64 + nth*16 + gid;
    auto f = [&](int k, int n) -> float {
        return (k < Krows) ? W[(size_t)k*ld + n] : 0.f;
    };
    uint4 o;
    o.x = pkbf(f(k0+2*q,   na),   f(k0+2*q+1, na));
    o.y = pkbf(f(k0+2*q+8, na),   f(k0+2*q+9, na));
    o.z = pkbf(f(k0+2*q,   na+8), f(k0+2*q+1, na+8));
    o.w = pkbf(f(k0+2*q+8, na+8), f(k0+2*q+9, na+8));
    return o;
}

// static-row variant: K=160 rows of Wm1 with row map k<128 ? k : k+256
__device__ __forceinline__ uint4 packs(const float* __restrict__ Wm1, int i)
{
    int lane = i & 31;
    int nth  = (i >> 5) & 3;
    int rest = i >> 7;
    int ks = rest % 10;
    int ng = rest / 10;
    int q = lane & 3;
    int gid = lane >> 2;
    int k0 = ks * 16;
    int na = ng*64 + nth*16 + gid;
    auto f = [&](int k, int n) -> float {
        int r = (k < 128) ? k : k + 256;
        return Wm1[(size_t)r*128 + n];
    };
    uint4 o;
    o.x = pkbf(f(k0+2*q,   na),   f(k0+2*q+1, na));
    o.y = pkbf(f(k0+2*q+8, na),   f(k0+2*q+9, na));
    o.z = pkbf(f(k0+2*q,   na+8), f(k0+2*q+1, na+8));
    o.w = pkbf(f(k0+2*q+8, na+8), f(k0+2*q+9, na+8));
    return o;
}

// ---------------------------------------------------------------------------
// Kernel 1: blocks [0, NODES/NPB): frames + points + packed static A rows,
//           NPB nodes/CTA. blocks [NODES/NPB, +64): weight packing.
// ---------------------------------------------------------------------------
#define NPB 4
__global__ void node_prep_kernel(const float* __restrict__ hV_g,
                                 const float* __restrict__ X,
                                 const float* __restrict__ Wp,
                                 const float* __restrict__ bp,
                                 const float* __restrict__ Wm1,
                                 const float* __restrict__ Wm2,
                                 const float* __restrict__ Wm3,
                                 const float* __restrict__ Wd1,
                                 const float* __restrict__ Wd2)
{
    int t = threadIdx.x;
    if (blockIdx.x >= NODES/NPB) {
        // ---- weight packing blocks ----
        int i = (blockIdx.x - NODES/NPB) * 128 + t;   // 0..8191
        if (i < 2*16*4*32) g_w1e_b[i] = packb(Wm1 + 128*128, 128, 256, i, 16);
        if (i < 2*8*4*32) {
            g_w2_b[i] = packb(Wm2, 128, 128, i, 8);
            g_w3_b[i] = packb(Wm3, 128, 128, i, 8);
        }
        if (i < 2*3*4*32)  g_w1g_b[i] = packb(Wm1 + 416*128, 128, 40, i, 3);
        if (i < 2*10*4*32) g_ws_b[i] = packs(Wm1, i);
        if (i < 8*8*4*32)  g_wd1_b[i] = packb(Wd1, 512, 128, i, 8);
        if (i < 2*32*4*32) g_wd2_b[i] = packb(Wd2, 128, 512, i, 32);
        return;
    }

    int node0 = blockIdx.x * NPB;
    __shared__ float hvS[NPB*128];
    __shared__ float plS[NPB*24];
    __shared__ float plnS[NPB*8];
    __shared__ float RnS[NPB*9];
    __shared__ float tnS[NPB*3];

    #pragma unroll
    for (int nn = 0; nn < NPB; ++nn)
        hvS[nn*128 + t] = hV_g[(size_t)(node0+nn)*DD + t];
    __syncthreads();

    if (t < NPB*24) {
        int nn = t / 24, j = t % 24;
        float acc = bp[j];
        #pragma unroll 8
        for (int d = 0; d < DD; ++d) acc += hvS[nn*128 + d] * Wp[d*24 + j];
        plS[nn*24 + j] = acc;
    } else if (t < NPB*24 + NPB) {
        int nn = t - NPB*24;
        const float* x = X + (size_t)(node0+nn)*9;
        float Xn0=x[0],Xn1=x[1],Xn2=x[2];
        float Xa0=x[3],Xa1=x[4],Xa2=x[5];
        float Xc0=x[6],Xc1=x[7],Xc2=x[8];
        float v10=Xc0-Xa0, v11=Xc1-Xa1, v12=Xc2-Xa2;
        float v20=Xn0-Xa0, v21=Xn1-Xa1, v22=Xn2-Xa2;
        float inv1 = rsqrtf(v10*v10+v11*v11+v12*v12+1e-8f);
        float e10=v10*inv1, e11=v11*inv1, e12=v12*inv1;
        float dp = e10*v20+e11*v21+e12*v22;
        float u20=v20-e10*dp, u21=v21-e11*dp, u22=v22-e12*dp;
        float inv2 = rsqrtf(u20*u20+u21*u21+u22*u22+1e-8f);
        float e20=u20*inv2, e21=u21*inv2, e22=u22*inv2;
        float e30=e11*e22-e12*e21;
        float e31=e12*e20-e10*e22;
        float e32=e10*e21-e11*e20;
        float* Rn = RnS + nn*9;
        Rn[0]=e10; Rn[1]=e20; Rn[2]=e30;
        Rn[3]=e11; Rn[4]=e21; Rn[5]=e31;
        Rn[6]=e12; Rn[7]=e22; Rn[8]=e32;
        tnS[nn*3+0]=Xa0*0.1f; tnS[nn*3+1]=Xa1*0.1f; tnS[nn*3+2]=Xa2*0.1f;
    }
    __syncthreads();

    if (t < NPB*8) {
        int nn = t >> 3, p = t & 7;
        float a=plS[nn*24+p*3+0], b=plS[nn*24+p*3+1], c=plS[nn*24+p*3+2];
        plnS[nn*8+p] = sqrtf(a*a+b*b+c*c + 1e-8f);
    }
    __syncthreads();

    if (t < NPB*24) {
        int nn = t / 24, j = t % 24;
        int p = j/3, i = j%3;
        const float* Rn = RnS + nn*9;
        float pg = tnS[nn*3+i] + Rn[i*3+0]*plS[nn*24+p*3+0]
                 + Rn[i*3+1]*plS[nn*24+p*3+1] + Rn[i*3+2]*plS[nn*24+p*3+2];
        g_pg[(size_t)(node0+nn)*24 + t] = pg;
    }
    if (t < NPB*9) g_R[(size_t)node0*9 + t] = RnS[t];
    if (t < NPB*3) g_t[(size_t)node0*3 + t] = tnS[t];

    // packed static A rows: hv pairs (64 u32), pl pairs (12), pln pairs (4)
    for (int idx = t; idx < NPB*80; idx += 128) {
        int nn = idx / 80, c = idx % 80;
        uint32_t v;
        if (c < 64)      v = pkbf(hvS[nn*128 + 2*c],       hvS[nn*128 + 2*c + 1]);
        else if (c < 76) { int j = (c-64)*2; v = pkbf(plS[nn*24 + j], plS[nn*24 + j + 1]); }
        else             { int p = (c-76)*2; v = pkbf(plnS[nn*8 + p], plnS[nn*8 + p + 1]); }
        g_sA[(size_t)(node0+nn)*80 + c] = v;
    }
}

// ---------------------------------------------------------------------------
// bf16 m16n8k16 mma helpers
// ---------------------------------------------------------------------------
__device__ __forceinline__ void mma16816(float (&d)[4],
                                         uint32_t a0, uint32_t a1,
                                         uint32_t a2, uint32_t a3,
                                         uint32_t b0, uint32_t b1)
{
    asm volatile(
        "mma.sync.aligned.m16n8k16.row.col.f32.bf16.bf16.f32 "
        "{%0,%1,%2,%3},{%4,%5,%6,%7},{%8,%9},{%0,%1,%2,%3};"
        : "+f"(d[0]), "+f"(d[1]), "+f"(d[2]), "+f"(d[3])
        : "r"(a0), "r"(a1), "r"(a2), "r"(a3), "r"(b0), "r"(b1));
}

template<int KSTEPS>
__device__ __forceinline__ void mma_blk(float (*acc)[4],
                                        const uint32_t* r0, const uint32_t* r1,
                                        const uint4* __restrict__ frag)
{
    #pragma unroll
    for (int ks = 0; ks < KSTEPS; ++ks) {
        uint32_t a0 = r0[ks*8], a1 = r1[ks*8], a2 = r0[ks*8+4], a3 = r1[ks*8+4];
        const uint4* fb = frag + ks*128;
        #pragma unroll
        for (int nth = 0; nth < 4; ++nth) {
            uint4 b = fb[nth*32];
            mma16816(acc[2*nth],   a0, a1, a2, a3, b.x, b.y);
            mma16816(acc[2*nth+1], a0, a1, a2, a3, b.z, b.w);
        }
    }
}

__device__ __forceinline__ float warp_sum(float v) {
    #pragma unroll
    for (int o = 16; o; o >>= 1) v += __shfl_xor_sync(0xffffffffu, v, o);
    return v;
}

// ---------------------------------------------------------------------------
// Kernel 1b: s1 = staticA @ Ws + bm1 via bf16 MMA, 64 nodes/CTA (grid 64)
// ---------------------------------------------------------------------------
#define SAST 84
__global__ void __launch_bounds__(256, 2)
s1_kernel(const float* __restrict__ bm1)
{
    __shared__ uint32_t sA[64*SAST];

    int node0 = blockIdx.x * 64;
    int t = threadIdx.x;
    int w = t >> 5, lane = t & 31;
    int mh = w & 3, ng = w >> 2;
    int gid = lane >> 2, q = lane & 3;

    {
        const uint4* src = (const uint4*)(g_sA + (size_t)node0*80);
        #pragma unroll
        for (int i = t; i < 64*20; i += 256) {
            int node = i / 20, c = i % 20;
            *(uint4*)(sA + node*SAST + c*4) = src[i];
        }
    }
    __syncthreads();

    float acc[8][4];
    #pragma unroll
    for (int nt = 0; nt < 8; ++nt)
        #pragma unroll
        for (int i = 0; i < 4; ++i) acc[nt][i] = 0.f;

    const uint32_t* r0 = sA + (mh*16 + gid)*SAST + q;
    const uint32_t* r1 = r0 + 8*SAST;
    mma_blk<10>(acc, r0, r1, g_ws_b + ng*(10*128) + lane);

    int r0i = mh*16 + gid, r1i = r0i + 8;
    #pragma unroll
    for (int nt = 0; nt < 8; ++nt) {
        int cb = ng*64 + nt*8 + 2*q;
        float ba = bm1[cb], bb = bm1[cb+1];
        g_s1[(size_t)(node0+r0i)*HH + cb]     = acc[nt][0] + ba;
        g_s1[(size_t)(node0+r0i)*HH + cb + 1] = acc[nt][1] + bb;
        g_s1[(size_t)(node0+r1i)*HH + cb]     = acc[nt][2] + ba;
        g_s1[(size_t)(node0+r1i)*HH + cb + 1] = acc[nt][3] + bb;
    }
}

// msg_kernel smem layout (u32 units)
#define AST 68          // 64 data u32 (128 bf16) + 4 pad
#define GST 28          // 24 data u32 (48 bf16) + 4 pad
#define SM_BUFA  0      // 64*68 = 4352 : h_E -> relu(L1)
#define SM_BUFB  4352   // nbr_hV -> relu(L2)
#define SM_GEO   8704   // 64*28 = 1792
#define SM_HV    10496  // 256 (fp32)
#define SM_S1    10752  // 256
#define SM_RN    11008  // 24
#define SM_TN    11032  // 8
#define SM_PGN   11040  // 48
#define SM_MA    11088  // 64
#define SM_RED   11152  // 16
#define SM_PD    11168  // 1024
#define SM_EIX   12192  // 64
#define SM_U32   12256
#define SMEM_BYTES (SM_U32*4)

// ---------------------------------------------------------------------------
// Kernel 2: 2 nodes per CTA, bf16 MMA message MLP, ends at LN1 -> g_hs.
// ---------------------------------------------------------------------------
__global__ void __launch_bounds__(256, 3)
msg_kernel(const float* __restrict__ hV_g, const float* __restrict__ hE_g,
           const float* __restrict__ maskA_g,
           const float* __restrict__ bm2, const float* __restrict__ bm3,
           const float* __restrict__ g1, const float* __restrict__ be1,
           const int* __restrict__ Eidx,
           float* __restrict__ outE, long long availE)
{
    extern __shared__ float smf[];
    uint32_t* smu = (uint32_t*)smf;
    uint32_t* bufA = smu + SM_BUFA;
    uint32_t* bufB = smu + SM_BUFB;
    uint32_t* geoU = smu + SM_GEO;
    float* hv  = smf + SM_HV;
    float* s1  = smf + SM_S1;
    float* Rn  = smf + SM_RN;
    float* tn  = smf + SM_TN;
    float* pgn = smf + SM_PGN;
    float* mA  = smf + SM_MA;
    float* red = smf + SM_RED;
    float* pd  = smf + SM_PD;
    int*   eix = (int*)(smu + SM_EIX);

    int node0 = blockIdx.x * 2;
    int batch = node0 / NN;
    int t = threadIdx.x;
    int w = t >> 5, lane = t & 31;
    int mh = w & 3, ng = w >> 2;
    int gid = lane >> 2, q = lane & 3;

    hv[t] = hV_g[(size_t)node0*DD + t];
    s1[t] = g_s1[(size_t)node0*HH + t];
    if (t < 48) pgn[t] = g_pg[(size_t)node0*24 + t];
    else if (t < 66) Rn[t-48] = g_R[(size_t)node0*9 + (t-48)];
    else if (t < 72) tn[t-66] = g_t[(size_t)node0*3 + (t-66)];
    if (t >= 128 && t < 192) mA[t-128] = maskA_g[(size_t)node0*KK + (t-128)];
    else if (t >= 192) eix[t-192] = Eidx[(size_t)node0*KK + (t-192)];
    __syncthreads();

    // ============ fused staging: h_E->bufA (+passthrough), nbr->bufB, geo ==
    {
        long long ebase = (long long)node0 * KK * DD;
        const float4* src = (const float4*)(hE_g + ebase);
        float4* dst = (float4*)(outE + ebase);
        bool full = (ebase + 2*KK*DD) <= availE;
        #pragma unroll
        for (int i = 0; i < 8; ++i) {
            int f4 = t + i*256;          // 0..2047
            float4 v = src[f4];
            if (full || (ebase + (long long)f4*4 + 4) <= availE) dst[f4] = v;
            int e = f4 >> 5, cp = (f4 & 31) * 2;
            uint2 o;
            o.x = pkbf(v.x, v.y);
            o.y = pkbf(v.z, v.w);
            *(uint2*)(bufA + e*AST + cp) = o;
        }
    }
    // nbr_hV gather -> bufB
    #pragma unroll
    for (int ii = 0; ii < 8; ++ii) {
        int e = w + ii*8;
        int j = eix[e];
        const float4* src = (const float4*)(hV_g + (size_t)(batch*NN + j)*DD);
        float4 v = src[lane];
        uint2 o;
        o.x = pkbf(v.x, v.y);
        o.y = pkbf(v.z, v.w);
        *(uint2*)(bufB + e*AST + lane*2) = o;
    }
    // geometry rows
    #pragma unroll
    for (int ii = 0; ii < 8; ++ii) {
        int e = w + ii*8;
        if (lane < 8) {
            int p = lane;
            int nn = e >> 5;
            int j = eix[e];
            const float* qg = g_pg + (size_t)(batch*NN + j)*24 + p*3;
            float q0 = qg[0], q1 = qg[1], q2 = qg[2];
            const float* R = Rn + nn*9;
            float d0 = pgn[nn*24+p*3+0]-q0, d1 = pgn[nn*24+p*3+1]-q1, d2 = pgn[nn*24+p*3+2]-q2;
            float cc0 = q0 - tn[nn*3+0], cc1 = q1 - tn[nn*3+1], cc2 = q2 - tn[nn*3+2];
            float l0 = R[0]*cc0 + R[3]*cc1 + R[6]*cc2;
            float l1 = R[1]*cc0 + R[4]*cc1 + R[7]*cc2;
            float l2 = R[2]*cc0 + R[5]*cc1 + R[8]*cc2;
            __nv_bfloat16* row = (__nv_bfloat16*)(geoU + e*GST);
            row[p*3+0] = __float2bfloat16_rn(l0);
            row[p*3+1] = __float2bfloat16_rn(l1);
            row[p*3+2] = __float2bfloat16_rn(l2);
            row[24+p] = __float2bfloat16_rn(sqrtf(l0*l0+l1*l1+l2*l2 + 1e-8f));
            row[32+p] = __float2bfloat16_rn(sqrtf(d0*d0+d1*d1+d2*d2 + 1e-8f));
            if (p == 0) {
                uint32_t* ru = geoU + e*GST;
                ru[20] = 0u; ru[21] = 0u; ru[22] = 0u; ru[23] = 0u;
            }
        }
    }
    __syncthreads();

    const uint32_t* a_r0 = bufA + (mh*16 + gid)*AST + q;
    const uint32_t* a_r1 = a_r0 + 8*AST;
    const uint32_t* b_r0 = bufB + (mh*16 + gid)*AST + q;
    const uint32_t* b_r1 = b_r0 + 8*AST;

    // ============ layer 1: A (h_E) + B (nbr) + geo, back-to-back ============
    float acc[8][4];
    #pragma unroll
    for (int nt = 0; nt < 8; ++nt)
        #pragma unroll
        for (int i = 0; i < 4; ++i) acc[nt][i] = 0.f;

    mma_blk<8>(acc, a_r0, a_r1, g_w1e_b + ng*(16*128) + lane);
    mma_blk<8>(acc, b_r0, b_r1, g_w1e_b + ng*(16*128) + 8*128 + lane);
    {
        const uint32_t* g_r0 = geoU + (mh*16 + gid)*GST + q;
        mma_blk<3>(acc, g_r0, g_r0 + 8*GST, g_w1g_b + ng*(3*128) + lane);
    }
    __syncthreads();   // all reads of bufA / bufB complete

    // add static part + relu, store bf16 to bufA (h_E dead)
    {
        int e0r = mh*16 + gid;
        const float* s1n = s1 + (mh>>1)*128;
        #pragma unroll
        for (int nt = 0; nt < 8; ++nt) {
            int cb = ng*64 + nt*8 + 2*q;
            float sa = s1n[cb], sb = s1n[cb+1];
            bufA[e0r*AST + (cb>>1)] =
                pkbf(fmaxf(acc[nt][0] + sa, 0.f), fmaxf(acc[nt][1] + sb, 0.f));
            bufA[(e0r+8)*AST + (cb>>1)] =
                pkbf(fmaxf(acc[nt][2] + sa, 0.f), fmaxf(acc[nt][3] + sb, 0.f));
        }
    }
    __syncthreads();

    // ============ layer 2 (reads bufA, writes bufB — nbr rows dead) ========
    #pragma unroll
    for (int nt = 0; nt < 8; ++nt)
        #pragma unroll
        for (int i = 0; i < 4; ++i) acc[nt][i] = 0.f;
    mma_blk<8>(acc, a_r0, a_r1, g_w2_b + ng*(8*128) + lane);
    // no barrier needed: bufB reads all completed before post-L1 barrier,
    // and writing bufB does not conflict with other warps' L2 reads of bufA.
    {
        int e0r = mh*16 + gid;
        #pragma unroll
        for (int nt = 0; nt < 8; ++nt) {
            int cb = ng*64 + nt*8 + 2*q;
            float ba = bm2[cb], bb = bm2[cb+1];
            bufB[e0r*AST + (cb>>1)] =
                pkbf(fmaxf(acc[nt][0] + ba, 0.f), fmaxf(acc[nt][1] + bb, 0.f));
            bufB[(e0r+8)*AST + (cb>>1)] =
                pkbf(fmaxf(acc[nt][2] + ba, 0.f), fmaxf(acc[nt][3] + bb, 0.f));
        }
    }
    __syncthreads();

    // ============ layer 3 (reads bufB) + masked partial mean ===============
    #pragma unroll
    for (int nt = 0; nt < 8; ++nt)
        #pragma unroll
        for (int i = 0; i < 4; ++i) acc[nt][i] = 0.f;
    mma_blk<8>(acc, b_r0, b_r1, g_w3_b + ng*(8*128) + lane);
    {
        float mk0 = mA[mh*16 + gid], mk1 = mA[mh*16 + gid + 8];
        #pragma unroll
        for (int nt = 0; nt < 8; ++nt) {
            int cb = ng*64 + nt*8 + 2*q;
            float ba = bm3[cb], bb = bm3[cb+1];
            float ve = (acc[nt][0] + ba)*mk0 + (acc[nt][2] + ba)*mk1;
            float vo = (acc[nt][1] + bb)*mk0 + (acc[nt][3] + bb)*mk1;
            #pragma unroll
            for (int o = 4; o <= 16; o <<= 1) {
                ve += __shfl_xor_sync(0xffffffffu, ve, o);
                vo += __shfl_xor_sync(0xffffffffu, vo, o);
            }
            if (gid == 0) {
                pd[mh*128 + cb] = ve;
                pd[mh*128 + cb + 1] = vo;
            }
        }
    }
    __syncthreads();

    // ---------------- LN1 for both nodes -> g_hs ----------------
    int nodeL = t >> 7, c = t & 127;
    float x, dx;
    {
        float nm = (pd[nodeL*256 + c] + pd[nodeL*256 + 128 + c]) * (1.0f/KK);
        x = hv[nodeL*128 + c] + nm;
        float sA = warp_sum(x);
        if (!lane) red[w] = sA;
    }
    __syncthreads();
    {
        float mu = (red[nodeL*4+0]+red[nodeL*4+1]+red[nodeL*4+2]+red[nodeL*4+3]) * (1.0f/HH);
        dx = x - mu;
        float sB = warp_sum(dx*dx);
        __syncwarp();
        if (!lane) red[8+w] = sB;
    }
    __syncthreads();
    {
        float var = (red[8+nodeL*4]+red[9+nodeL*4]+red[10+nodeL*4]+red[11+nodeL*4]) * (1.0f/HH);
        g_hs[(size_t)(node0+nodeL)*HH + c] = dx * rsqrtf(var + 1e-5f) * g1[c] + be1[c];
    }
}

// dense kernel smem layout (u32 units), 16 nodes / CTA
#define D1ST 260       // 256 data u32 (512 bf16) + 4 pad
#define DM_HSB 0       // 16*68 = 1088
#define DM_D1B 1088    // 16*260 = 4160
#define DM_HSF 5248    // 2048 (fp32)
#define DM_X2  7296    // 2048 (fp32)
#define DM_U32 9344
#define DSMEM_BYTES (DM_U32*4)

// ---------------------------------------------------------------------------
// Kernel 3: dense FFN + LN2 + mask, 16 nodes per CTA (grid 256), bf16 MMA.
// dense1: warp w owns cols w*64..w*64+63 (one m-tile of 16 rows).
// dense2: warp w owns cols w*16..w*16+15 (ng2 = w>>2, nth2 = w&3), K=512.
// ---------------------------------------------------------------------------
__global__ void __launch_bounds__(256, 2)
dense_kernel(const float* __restrict__ maskV_g,
             const float* __restrict__ bd1, const float* __restrict__ bd2,
             const float* __restrict__ g2, const float* __restrict__ be2,
             float* __restrict__ out)
{
    extern __shared__ float smf[];
    uint32_t* smu = (uint32_t*)smf;
    uint32_t* hsb = smu + DM_HSB;
    uint32_t* d1b = smu + DM_D1B;
    float* hsf = smf + DM_HSF;
    float* x2s = smf + DM_X2;

    int node0 = blockIdx.x * 16;
    int t = threadIdx.x;
    int w = t >> 5, lane = t & 31;
    int gid = lane >> 2, q = lane & 3;

    // stage hs: fp32 copy + bf16 pack (16 rows x 128)
    {
        const float2* src = (const float2*)(g_hs + (size_t)node0*HH);
        #pragma unroll
        for (int i = t; i < 1024; i += 256) {
            float2 v = src[i];
            int row = i >> 6, cp = i & 63;
            hsf[row*128 + cp*2]     = v.x;
            hsf[row*128 + cp*2 + 1] = v.y;
            hsb[row*AST + cp] = pkbf(v.x, v.y);
        }
    }
    __syncthreads();

    const uint32_t* a_r0 = hsb + gid*AST + q;
    const uint32_t* a_r1 = a_r0 + 8*AST;

    // ---------------- dense1: 128 -> 512, relu, bf16 out ----------------
    {
        float acc[8][4];
        #pragma unroll
        for (int nt = 0; nt < 8; ++nt)
            #pragma unroll
            for (int i = 0; i < 4; ++i) acc[nt][i] = 0.f;
        mma_blk<8>(acc, a_r0, a_r1, g_wd1_b + w*(8*128) + lane);
        #pragma unroll
        for (int nt = 0; nt < 8; ++nt) {
            int cb = w*64 + nt*8 + 2*q;
            float ba = bd1[cb], bb = bd1[cb+1];
            d1b[gid*D1ST + (cb>>1)] =
                pkbf(fmaxf(acc[nt][0] + ba, 0.f), fmaxf(acc[nt][1] + bb, 0.f));
            d1b[(gid+8)*D1ST + (cb>>1)] =
                pkbf(fmaxf(acc[nt][2] + ba, 0.f), fmaxf(acc[nt][3] + bb, 0.f));
        }
    }
    __syncthreads();

    // ---------------- dense2: 512 -> 128, + bd2 + residual ----------------
    {
        float acc[2][4];
        #pragma unroll
        for (int nt = 0; nt < 2; ++nt)
            #pragma unroll
            for (int i = 0; i < 4; ++i) acc[nt][i] = 0.f;
        const uint32_t* d_r0 = d1b + gid*D1ST + q;
        const uint32_t* d_r1 = d_r0 + 8*D1ST;
        int ng2 = w >> 2, nth2 = w & 3;
        const uint4* frag = g_wd2_b + ng2*(32*128) + lane;
        #pragma unroll 8
        for (int ks = 0; ks < 32; ++ks) {
            uint32_t a0 = d_r0[ks*8], a1 = d_r1[ks*8], a2 = d_r0[ks*8+4], a3 = d_r1[ks*8+4];
            uint4 b = frag[ks*128 + nth2*32];
            mma16816(acc[0], a0, a1, a2, a3, b.x, b.y);
            mma16816(acc[1], a0, a1, a2, a3, b.z, b.w);
        }
        int r0 = gid, r1 = gid + 8;
        #pragma unroll
        for (int nt = 0; nt < 2; ++nt) {
            int cb = ng2*64 + nth2*16 + nt*8 + 2*q;
            float ba = bd2[cb], bb = bd2[cb+1];
            x2s[r0*128 + cb]     = acc[nt][0] + ba + hsf[r0*128 + cb];
            x2s[r0*128 + cb + 1] = acc[nt][1] + bb + hsf[r0*128 + cb + 1];
            x2s[r1*128 + cb]     = acc[nt][2] + ba + hsf[r1*128 + cb];
            x2s[r1*128 + cb + 1] = acc[nt][3] + bb + hsf[r1*128 + cb + 1];
        }
    }
    __syncthreads();

    // ---------------- LN2 + mask: warp w handles nodes w*2, w*2+1 ----------
    #pragma unroll
    for (int nn = 0; nn < 2; ++nn) {
        int row = w*2 + nn;
        float v0 = x2s[row*128 + lane];
        float v1 = x2s[row*128 + lane + 32];
        float v2 = x2s[row*128 + lane + 64];
        float v3 = x2s[row*128 + lane + 96];
        float mu = warp_sum(v0+v1+v2+v3) * (1.0f/HH);
        float d0 = v0-mu, d1 = v1-mu, d2 = v2-mu, d3 = v3-mu;
        float var = warp_sum(d0*d0+d1*d1+d2*d2+d3*d3) * (1.0f/HH);
        float rs = rsqrtf(var + 1e-5f);
        float mk = maskV_g[node0 + row];
        float* o = out + (size_t)(node0 + row)*HH;
        o[lane]      = (d0*rs*g2[lane]      + be2[lane])      * mk;
        o[lane + 32] = (d1*rs*g2[lane + 32] + be2[lane + 32]) * mk;
        o[lane + 64] = (d2*rs*g2[lane + 64] + be2[lane + 64]) * mk;
        o[lane + 96] = (d3*rs*g2[lane + 96] + be2[lane + 96]) * mk;
    }
}

// ---------------------------------------------------------------------------
extern "C" void kernel_launch(void* const* d_in, const int* in_sizes, int n_in,
                              void* d_out, int out_size)
{
    const float* hV    = (const float*)d_in[0];
    const float* hE    = (const float*)d_in[1];
    const float* X     = (const float*)d_in[2];
    const float* maskV = (const float*)d_in[3];
    const float* maskA = (const float*)d_in[4];
    const float* Wp    = (const float*)d_in[5];
    const float* bp    = (const float*)d_in[6];
    const float* Wm1   = (const float*)d_in[7];
    const float* bm1   = (const float*)d_in[8];
    const float* Wm2   = (const float*)d_in[9];
    const float* bm2   = (const float*)d_in[10];
    const float* Wm3   = (const float*)d_in[11];
    const float* bm3   = (const float*)d_in[12];
    const float* g1    = (const float*)d_in[13];
    const float* be1   = (const float*)d_in[14];
    const float* Wd1   = (const float*)d_in[15];
    const float* bd1   = (const float*)d_in[16];
    const float* Wd2   = (const float*)d_in[17];
    const float* bd2   = (const float*)d_in[18];
    const float* g2    = (const float*)d_in[19];
    const float* be2   = (const float*)d_in[20];
    const int*   Eidx  = (const int*)d_in[21];
    float* out = (float*)d_out;

    cudaFuncSetAttribute(msg_kernel, cudaFuncAttributeMaxDynamicSharedMemorySize, SMEM_BYTES);
    cudaFuncSetAttribute(dense_kernel, cudaFuncAttributeMaxDynamicSharedMemorySize, DSMEM_BYTES);

    long long hcount = (long long)NODES * HH;
    long long availE = (long long)out_size - hcount;
    if (availE < 0) availE = 0;
    long long emax = (long long)BB*NN*KK*DD;
    if (availE > emax) availE = emax;

    node_prep_kernel<<<NODES/NPB + 64, 128>>>(hV, X, Wp, bp, Wm1,
                                              Wm2, Wm3, Wd1, Wd2);
    s1_kernel<<<NODES/64, 256>>>(bm1);
    msg_kernel<<<NODES/2, 256, SMEM_BYTES>>>(hV, hE, maskA, bm2, bm3,
                                             g1, be1, Eidx,
                                             out + hcount, availE);
    dense_kernel<<<NODES/16, 256, DSMEM_BYTES>>>(maskV, bd1, bd2, g2, be2, out);
}

// round 14
// speedup vs baseline: 1.0303x; 1.0303x over previous
#include <cuda_runtime.h>
#include <cuda_bf16.h>
#include <math.h>
#include <stdint.h>

#define BB 8
#define NN 512
#define KK 32
#define DD 128
#define HH 128
#define PP 8
#define NODES (BB*NN)

// Scratch (allocation-free rule: __device__ globals)
__device__ float g_pg[NODES*PP*3];
__device__ float g_R[NODES*9];
__device__ float g_t[NODES*3];
__device__ float g_s1[NODES*HH];        // static layer-1 pre-activation (incl bias)
__device__ float g_hs[NODES*HH];        // post-LN1 hidden state
__device__ uint32_t g_sA[NODES*80];     // bf16-packed static A rows: hv(64)|pl(12)|pln(4) u32

// fragment-packed bf16 weights: [ng][ks][nth][lane] -> uint4(b0a,b1a,b0b,b1b)
__device__ uint4 g_w1e_b[2*16*4*32];   // Wm1 rows 128..383 (K=256, KS=16)
__device__ uint4 g_w1g_b[2*3*4*32];    // Wm1 rows 416..455 (K=40->48, KS=3)
__device__ uint4 g_ws_b[2*10*4*32];    // Wm1 static rows (K=160, KS=10; row map k<128?k:k+256)
__device__ uint4 g_w2_b[2*8*4*32];     // Wm2 (K=128, KS=8)
__device__ uint4 g_w3_b[2*8*4*32];     // Wm3
__device__ uint4 g_wd1_b[8*8*4*32];    // Wd1 (K=128, N=512: 8 n-groups, KS=8)
__device__ uint4 g_wd2_b[2*32*4*32];   // Wd2 (K=512, N=128: KS=32)

__device__ __forceinline__ uint32_t pkbf(float a, float b) {
    __nv_bfloat162 h = __floats2bfloat162_rn(a, b);
    return *reinterpret_cast<uint32_t*>(&h);
}

// ---------------------------------------------------------------------------
// weight packing helper (bf16 mma-fragment order)
// ---------------------------------------------------------------------------
__device__ __forceinline__ uint4 packb(const float* __restrict__ W, int ld,
                                       int Krows, int i, int KS)
{
    int lane = i & 31;
    int nth  = (i >> 5) & 3;
    int rest = i >> 7;
    int ks = rest % KS;
    int ng = rest / KS;
    int q = lane & 3;
    int gid = lane >> 2;
    int k0 = ks * 16;
    int na = ng*64 + nth*16 + gid;
    auto f = [&](int k, int n) -> float {
        return (k < Krows) ? W[(size_t)k*ld + n] : 0.f;
    };
    uint4 o;
    o.x = pkbf(f(k0+2*q,   na),   f(k0+2*q+1, na));
    o.y = pkbf(f(k0+2*q+8, na),   f(k0+2*q+9, na));
    o.z = pkbf(f(k0+2*q,   na+8), f(k0+2*q+1, na+8));
    o.w = pkbf(f(k0+2*q+8, na+8), f(k0+2*q+9, na+8));
    return o;
}

// static-row variant: K=160 rows of Wm1 with row map k<128 ? k : k+256
__device__ __forceinline__ uint4 packs(const float* __restrict__ Wm1, int i)
{
    int lane = i & 31;
    int nth  = (i >> 5) & 3;
    int rest = i >> 7;
    int ks = rest % 10;
    int ng = rest / 10;
    int q = lane & 3;
    int gid = lane >> 2;
    int k0 = ks * 16;
    int na = ng*64 + nth*16 + gid;
    auto f = [&](int k, int n) -> float {
        int r = (k < 128) ? k : k + 256;
        return Wm1[(size_t)r*128 + n];
    };
    uint4 o;
    o.x = pkbf(f(k0+2*q,   na),   f(k0+2*q+1, na));
    o.y = pkbf(f(k0+2*q+8, na),   f(k0+2*q+9, na));
    o.z = pkbf(f(k0+2*q,   na+8), f(k0+2*q+1, na+8));
    o.w = pkbf(f(k0+2*q+8, na+8), f(k0+2*q+9, na+8));
    return o;
}

// ---------------------------------------------------------------------------
// Kernel 1: blocks [0, NODES/NPB): frames + points + packed static A rows,
//           NPB nodes/CTA. blocks [NODES/NPB, +64): weight packing.
// ---------------------------------------------------------------------------
#define NPB 4
__global__ void node_prep_kernel(const float* __restrict__ hV_g,
                                 const float* __restrict__ X,
                                 const float* __restrict__ Wp,
                                 const float* __restrict__ bp,
                                 const float* __restrict__ Wm1,
                                 const float* __restrict__ Wm2,
                                 const float* __restrict__ Wm3,
                                 const float* __restrict__ Wd1,
                                 const float* __restrict__ Wd2)
{
    int t = threadIdx.x;
    if (blockIdx.x >= NODES/NPB) {
        // ---- weight packing blocks ----
        int i = (blockIdx.x - NODES/NPB) * 128 + t;   // 0..8191
        if (i < 2*16*4*32) g_w1e_b[i] = packb(Wm1 + 128*128, 128, 256, i, 16);
        if (i < 2*8*4*32) {
            g_w2_b[i] = packb(Wm2, 128, 128, i, 8);
            g_w3_b[i] = packb(Wm3, 128, 128, i, 8);
        }
        if (i < 2*3*4*32)  g_w1g_b[i] = packb(Wm1 + 416*128, 128, 40, i, 3);
        if (i < 2*10*4*32) g_ws_b[i] = packs(Wm1, i);
        if (i < 8*8*4*32)  g_wd1_b[i] = packb(Wd1, 512, 128, i, 8);
        if (i < 2*32*4*32) g_wd2_b[i] = packb(Wd2, 128, 512, i, 32);
        return;
    }

    int node0 = blockIdx.x * NPB;
    __shared__ float hvS[NPB*128];
    __shared__ float plS[NPB*24];
    __shared__ float plnS[NPB*8];
    __shared__ float RnS[NPB*9];
    __shared__ float tnS[NPB*3];

    #pragma unroll
    for (int nn = 0; nn < NPB; ++nn)
        hvS[nn*128 + t] = hV_g[(size_t)(node0+nn)*DD + t];
    __syncthreads();

    if (t < NPB*24) {
        int nn = t / 24, j = t % 24;
        float acc = bp[j];
        #pragma unroll 8
        for (int d = 0; d < DD; ++d) acc += hvS[nn*128 + d] * Wp[d*24 + j];
        plS[nn*24 + j] = acc;
    } else if (t < NPB*24 + NPB) {
        int nn = t - NPB*24;
        const float* x = X + (size_t)(node0+nn)*9;
        float Xn0=x[0],Xn1=x[1],Xn2=x[2];
        float Xa0=x[3],Xa1=x[4],Xa2=x[5];
        float Xc0=x[6],Xc1=x[7],Xc2=x[8];
        float v10=Xc0-Xa0, v11=Xc1-Xa1, v12=Xc2-Xa2;
        float v20=Xn0-Xa0, v21=Xn1-Xa1, v22=Xn2-Xa2;
        float inv1 = rsqrtf(v10*v10+v11*v11+v12*v12+1e-8f);
        float e10=v10*inv1, e11=v11*inv1, e12=v12*inv1;
        float dp = e10*v20+e11*v21+e12*v22;
        float u20=v20-e10*dp, u21=v21-e11*dp, u22=v22-e12*dp;
        float inv2 = rsqrtf(u20*u20+u21*u21+u22*u22+1e-8f);
        float e20=u20*inv2, e21=u21*inv2, e22=u22*inv2;
        float e30=e11*e22-e12*e21;
        float e31=e12*e20-e10*e22;
        float e32=e10*e21-e11*e20;
        float* Rn = RnS + nn*9;
        Rn[0]=e10; Rn[1]=e20; Rn[2]=e30;
        Rn[3]=e11; Rn[4]=e21; Rn[5]=e31;
        Rn[6]=e12; Rn[7]=e22; Rn[8]=e32;
        tnS[nn*3+0]=Xa0*0.1f; tnS[nn*3+1]=Xa1*0.1f; tnS[nn*3+2]=Xa2*0.1f;
    }
    __syncthreads();

    if (t < NPB*8) {
        int nn = t >> 3, p = t & 7;
        float a=plS[nn*24+p*3+0], b=plS[nn*24+p*3+1], c=plS[nn*24+p*3+2];
        plnS[nn*8+p] = sqrtf(a*a+b*b+c*c + 1e-8f);
    }
    __syncthreads();

    if (t < NPB*24) {
        int nn = t / 24, j = t % 24;
        int p = j/3, i = j%3;
        const float* Rn = RnS + nn*9;
        float pg = tnS[nn*3+i] + Rn[i*3+0]*plS[nn*24+p*3+0]
                 + Rn[i*3+1]*plS[nn*24+p*3+1] + Rn[i*3+2]*plS[nn*24+p*3+2];
        g_pg[(size_t)(node0+nn)*24 + t] = pg;
    }
    if (t < NPB*9) g_R[(size_t)node0*9 + t] = RnS[t];
    if (t < NPB*3) g_t[(size_t)node0*3 + t] = tnS[t];

    // packed static A rows: hv pairs (64 u32), pl pairs (12), pln pairs (4)
    for (int idx = t; idx < NPB*80; idx += 128) {
        int nn = idx / 80, c = idx % 80;
        uint32_t v;
        if (c < 64)      v = pkbf(hvS[nn*128 + 2*c],       hvS[nn*128 + 2*c + 1]);
        else if (c < 76) { int j = (c-64)*2; v = pkbf(plS[nn*24 + j], plS[nn*24 + j + 1]); }
        else             { int p = (c-76)*2; v = pkbf(plnS[nn*8 + p], plnS[nn*8 + p + 1]); }
        g_sA[(size_t)(node0+nn)*80 + c] = v;
    }
}

// ---------------------------------------------------------------------------
// bf16 m16n8k16 mma helpers
// ---------------------------------------------------------------------------
__device__ __forceinline__ void mma16816(float (&d)[4],
                                         uint32_t a0, uint32_t a1,
                                         uint32_t a2, uint32_t a3,
                                         uint32_t b0, uint32_t b1)
{
    asm volatile(
        "mma.sync.aligned.m16n8k16.row.col.f32.bf16.bf16.f32 "
        "{%0,%1,%2,%3},{%4,%5,%6,%7},{%8,%9},{%0,%1,%2,%3};"
        : "+f"(d[0]), "+f"(d[1]), "+f"(d[2]), "+f"(d[3])
        : "r"(a0), "r"(a1), "r"(a2), "r"(a3), "r"(b0), "r"(b1));
}

template<int KSTEPS>
__device__ __forceinline__ void mma_blk(float (*acc)[4],
                                        const uint32_t* r0, const uint32_t* r1,
                                        const uint4* __restrict__ frag)
{
    #pragma unroll
    for (int ks = 0; ks < KSTEPS; ++ks) {
        uint32_t a0 = r0[ks*8], a1 = r1[ks*8], a2 = r0[ks*8+4], a3 = r1[ks*8+4];
        const uint4* fb = frag + ks*128;
        #pragma unroll
        for (int nth = 0; nth < 4; ++nth) {
            uint4 b = fb[nth*32];
            mma16816(acc[2*nth],   a0, a1, a2, a3, b.x, b.y);
            mma16816(acc[2*nth+1], a0, a1, a2, a3, b.z, b.w);
        }
    }
}

__device__ __forceinline__ float warp_sum(float v) {
    #pragma unroll
    for (int o = 16; o; o >>= 1) v += __shfl_xor_sync(0xffffffffu, v, o);
    return v;
}

// ---------------------------------------------------------------------------
// Kernel 1b: s1 = staticA @ Ws + bm1 via bf16 MMA, 64 nodes/CTA (grid 64)
// ---------------------------------------------------------------------------
#define SAST 84
__global__ void __launch_bounds__(256, 2)
s1_kernel(const float* __restrict__ bm1)
{
    __shared__ uint32_t sA[64*SAST];

    int node0 = blockIdx.x * 64;
    int t = threadIdx.x;
    int w = t >> 5, lane = t & 31;
    int mh = w & 3, ng = w >> 2;
    int gid = lane >> 2, q = lane & 3;

    {
        const uint4* src = (const uint4*)(g_sA + (size_t)node0*80);
        #pragma unroll
        for (int i = t; i < 64*20; i += 256) {
            int node = i / 20, c = i % 20;
            *(uint4*)(sA + node*SAST + c*4) = src[i];
        }
    }
    __syncthreads();

    float acc[8][4];
    #pragma unroll
    for (int nt = 0; nt < 8; ++nt)
        #pragma unroll
        for (int i = 0; i < 4; ++i) acc[nt][i] = 0.f;

    const uint32_t* r0 = sA + (mh*16 + gid)*SAST + q;
    const uint32_t* r1 = r0 + 8*SAST;
    mma_blk<10>(acc, r0, r1, g_ws_b + ng*(10*128) + lane);

    int r0i = mh*16 + gid, r1i = r0i + 8;
    #pragma unroll
    for (int nt = 0; nt < 8; ++nt) {
        int cb = ng*64 + nt*8 + 2*q;
        float ba = bm1[cb], bb = bm1[cb+1];
        g_s1[(size_t)(node0+r0i)*HH + cb]     = acc[nt][0] + ba;
        g_s1[(size_t)(node0+r0i)*HH + cb + 1] = acc[nt][1] + bb;
        g_s1[(size_t)(node0+r1i)*HH + cb]     = acc[nt][2] + ba;
        g_s1[(size_t)(node0+r1i)*HH + cb + 1] = acc[nt][3] + bb;
    }
}

// msg_kernel smem layout (u32 units)
#define AST 68          // 64 data u32 (128 bf16) + 4 pad
#define GST 28          // 24 data u32 (48 bf16) + 4 pad
#define SM_BUFA  0      // 64*68 = 4352 : h_E -> relu(L1)
#define SM_BUFB  4352   // nbr_hV -> relu(L2)
#define SM_GEO   8704   // 64*28 = 1792
#define SM_HV    10496  // 256 (fp32)
#define SM_S1    10752  // 256
#define SM_RN    11008  // 24
#define SM_TN    11032  // 8
#define SM_PGN   11040  // 48
#define SM_MA    11088  // 64
#define SM_RED   11152  // 16
#define SM_PD    11168  // 1024
#define SM_EIX   12192  // 64
#define SM_U32   12256
#define SMEM_BYTES (SM_U32*4)

// ---------------------------------------------------------------------------
// Kernel 2: 2 nodes per CTA, bf16 MMA message MLP, ends at LN1 -> g_hs.
// (R12 structure: fused staging, barrier after L2 MMA before bufB store.)
// ---------------------------------------------------------------------------
__global__ void __launch_bounds__(256, 3)
msg_kernel(const float* __restrict__ hV_g, const float* __restrict__ hE_g,
           const float* __restrict__ maskA_g,
           const float* __restrict__ bm2, const float* __restrict__ bm3,
           const float* __restrict__ g1, const float* __restrict__ be1,
           const int* __restrict__ Eidx,
           float* __restrict__ outE, long long availE)
{
    extern __shared__ float smf[];
    uint32_t* smu = (uint32_t*)smf;
    uint32_t* bufA = smu + SM_BUFA;
    uint32_t* bufB = smu + SM_BUFB;
    uint32_t* geoU = smu + SM_GEO;
    float* hv  = smf + SM_HV;
    float* s1  = smf + SM_S1;
    float* Rn  = smf + SM_RN;
    float* tn  = smf + SM_TN;
    float* pgn = smf + SM_PGN;
    float* mA  = smf + SM_MA;
    float* red = smf + SM_RED;
    float* pd  = smf + SM_PD;
    int*   eix = (int*)(smu + SM_EIX);

    int node0 = blockIdx.x * 2;
    int batch = node0 / NN;
    int t = threadIdx.x;
    int w = t >> 5, lane = t & 31;
    int mh = w & 3, ng = w >> 2;
    int gid = lane >> 2, q = lane & 3;

    hv[t] = hV_g[(size_t)node0*DD + t];
    s1[t] = g_s1[(size_t)node0*HH + t];
    if (t < 48) pgn[t] = g_pg[(size_t)node0*24 + t];
    else if (t < 66) Rn[t-48] = g_R[(size_t)node0*9 + (t-48)];
    else if (t < 72) tn[t-66] = g_t[(size_t)node0*3 + (t-66)];
    if (t >= 128 && t < 192) mA[t-128] = maskA_g[(size_t)node0*KK + (t-128)];
    else if (t >= 192) eix[t-192] = Eidx[(size_t)node0*KK + (t-192)];
    __syncthreads();

    // ============ fused staging: h_E->bufA (+passthrough), nbr->bufB, geo ==
    {
        long long ebase = (long long)node0 * KK * DD;
        const float4* src = (const float4*)(hE_g + ebase);
        float4* dst = (float4*)(outE + ebase);
        bool full = (ebase + 2*KK*DD) <= availE;
        #pragma unroll
        for (int i = 0; i < 8; ++i) {
            int f4 = t + i*256;          // 0..2047
            float4 v = src[f4];
            if (full || (ebase + (long long)f4*4 + 4) <= availE) dst[f4] = v;
            int e = f4 >> 5, cp = (f4 & 31) * 2;
            uint2 o;
            o.x = pkbf(v.x, v.y);
            o.y = pkbf(v.z, v.w);
            *(uint2*)(bufA + e*AST + cp) = o;
        }
    }
    // nbr_hV gather -> bufB
    #pragma unroll
    for (int ii = 0; ii < 8; ++ii) {
        int e = w + ii*8;
        int j = eix[e];
        const float4* src = (const float4*)(hV_g + (size_t)(batch*NN + j)*DD);
        float4 v = src[lane];
        uint2 o;
        o.x = pkbf(v.x, v.y);
        o.y = pkbf(v.z, v.w);
        *(uint2*)(bufB + e*AST + lane*2) = o;
    }
    // geometry rows
    #pragma unroll
    for (int ii = 0; ii < 8; ++ii) {
        int e = w + ii*8;
        if (lane < 8) {
            int p = lane;
            int nn = e >> 5;
            int j = eix[e];
            const float* qg = g_pg + (size_t)(batch*NN + j)*24 + p*3;
            float q0 = qg[0], q1 = qg[1], q2 = qg[2];
            const float* R = Rn + nn*9;
            float d0 = pgn[nn*24+p*3+0]-q0, d1 = pgn[nn*24+p*3+1]-q1, d2 = pgn[nn*24+p*3+2]-q2;
            float cc0 = q0 - tn[nn*3+0], cc1 = q1 - tn[nn*3+1], cc2 = q2 - tn[nn*3+2];
            float l0 = R[0]*cc0 + R[3]*cc1 + R[6]*cc2;
            float l1 = R[1]*cc0 + R[4]*cc1 + R[7]*cc2;
            float l2 = R[2]*cc0 + R[5]*cc1 + R[8]*cc2;
            __nv_bfloat16* row = (__nv_bfloat16*)(geoU + e*GST);
            row[p*3+0] = __float2bfloat16_rn(l0);
            row[p*3+1] = __float2bfloat16_rn(l1);
            row[p*3+2] = __float2bfloat16_rn(l2);
            row[24+p] = __float2bfloat16_rn(sqrtf(l0*l0+l1*l1+l2*l2 + 1e-8f));
            row[32+p] = __float2bfloat16_rn(sqrtf(d0*d0+d1*d1+d2*d2 + 1e-8f));
            if (p == 0) {
                uint32_t* ru = geoU + e*GST;
                ru[20] = 0u; ru[21] = 0u; ru[22] = 0u; ru[23] = 0u;
            }
        }
    }
    __syncthreads();

    const uint32_t* a_r0 = bufA + (mh*16 + gid)*AST + q;
    const uint32_t* a_r1 = a_r0 + 8*AST;
    const uint32_t* b_r0 = bufB + (mh*16 + gid)*AST + q;
    const uint32_t* b_r1 = b_r0 + 8*AST;

    // ============ layer 1: A (h_E) + B (nbr) + geo, back-to-back ============
    float acc[8][4];
    #pragma unroll
    for (int nt = 0; nt < 8; ++nt)
        #pragma unroll
        for (int i = 0; i < 4; ++i) acc[nt][i] = 0.f;

    mma_blk<8>(acc, a_r0, a_r1, g_w1e_b + ng*(16*128) + lane);
    mma_blk<8>(acc, b_r0, b_r1, g_w1e_b + ng*(16*128) + 8*128 + lane);
    {
        const uint32_t* g_r0 = geoU + (mh*16 + gid)*GST + q;
        mma_blk<3>(acc, g_r0, g_r0 + 8*GST, g_w1g_b + ng*(3*128) + lane);
    }
    __syncthreads();   // all reads of bufA / bufB complete

    // add static part + relu, store bf16 to bufA (h_E dead)
    {
        int e0r = mh*16 + gid;
        const float* s1n = s1 + (mh>>1)*128;
        #pragma unroll
        for (int nt = 0; nt < 8; ++nt) {
            int cb = ng*64 + nt*8 + 2*q;
            float sa = s1n[cb], sb = s1n[cb+1];
            bufA[e0r*AST + (cb>>1)] =
                pkbf(fmaxf(acc[nt][0] + sa, 0.f), fmaxf(acc[nt][1] + sb, 0.f));
            bufA[(e0r+8)*AST + (cb>>1)] =
                pkbf(fmaxf(acc[nt][2] + sa, 0.f), fmaxf(acc[nt][3] + sb, 0.f));
        }
    }
    __syncthreads();

    // ============ layer 2 (reads bufA, writes bufB) ========================
    #pragma unroll
    for (int nt = 0; nt < 8; ++nt)
        #pragma unroll
        for (int i = 0; i < 4; ++i) acc[nt][i] = 0.f;
    mma_blk<8>(acc, a_r0, a_r1, g_w2_b + ng*(8*128) + lane);
    __syncthreads();   // scheduling fence: keeps bufB store after all L2 reads
    {
        int e0r = mh*16 + gid;
        #pragma unroll
        for (int nt = 0; nt < 8; ++nt) {
            int cb = ng*64 + nt*8 + 2*q;
            float ba = bm2[cb], bb = bm2[cb+1];
            bufB[e0r*AST + (cb>>1)] =
                pkbf(fmaxf(acc[nt][0] + ba, 0.f), fmaxf(acc[nt][1] + bb, 0.f));
            bufB[(e0r+8)*AST + (cb>>1)] =
                pkbf(fmaxf(acc[nt][2] + ba, 0.f), fmaxf(acc[nt][3] + bb, 0.f));
        }
    }
    __syncthreads();

    // ============ layer 3 (reads bufB) + masked partial mean ===============
    #pragma unroll
    for (int nt = 0; nt < 8; ++nt)
        #pragma unroll
        for (int i = 0; i < 4; ++i) acc[nt][i] = 0.f;
    mma_blk<8>(acc, b_r0, b_r1, g_w3_b + ng*(8*128) + lane);
    {
        float mk0 = mA[mh*16 + gid], mk1 = mA[mh*16 + gid + 8];
        #pragma unroll
        for (int nt = 0; nt < 8; ++nt) {
            int cb = ng*64 + nt*8 + 2*q;
            float ba = bm3[cb], bb = bm3[cb+1];
            float ve = (acc[nt][0] + ba)*mk0 + (acc[nt][2] + ba)*mk1;
            float vo = (acc[nt][1] + bb)*mk0 + (acc[nt][3] + bb)*mk1;
            #pragma unroll
            for (int o = 4; o <= 16; o <<= 1) {
                ve += __shfl_xor_sync(0xffffffffu, ve, o);
                vo += __shfl_xor_sync(0xffffffffu, vo, o);
            }
            if (gid == 0) {
                pd[mh*128 + cb] = ve;
                pd[mh*128 + cb + 1] = vo;
            }
        }
    }
    __syncthreads();

    // ---------------- LN1 for both nodes -> g_hs ----------------
    int nodeL = t >> 7, c = t & 127;
    float x, dx;
    {
        float nm = (pd[nodeL*256 + c] + pd[nodeL*256 + 128 + c]) * (1.0f/KK);
        x = hv[nodeL*128 + c] + nm;
        float sA = warp_sum(x);
        if (!lane) red[w] = sA;
    }
    __syncthreads();
    {
        float mu = (red[nodeL*4+0]+red[nodeL*4+1]+red[nodeL*4+2]+red[nodeL*4+3]) * (1.0f/HH);
        dx = x - mu;
        float sB = warp_sum(dx*dx);
        __syncwarp();
        if (!lane) red[8+w] = sB;
    }
    __syncthreads();
    {
        float var = (red[8+nodeL*4]+red[9+nodeL*4]+red[10+nodeL*4]+red[11+nodeL*4]) * (1.0f/HH);
        g_hs[(size_t)(node0+nodeL)*HH + c] = dx * rsqrtf(var + 1e-5f) * g1[c] + be1[c];
    }
}

// dense kernel smem layout (u32 units), 16 nodes / CTA
#define D1ST 260       // 256 data u32 (512 bf16) + 4 pad
#define DM_HSB 0       // 16*68 = 1088
#define DM_D1B 1088    // 16*260 = 4160
#define DM_HSF 5248    // 2048 (fp32)
#define DM_X2  7296    // 2048 (fp32)
#define DM_U32 9344
#define DSMEM_BYTES (DM_U32*4)

// ---------------------------------------------------------------------------
// Kernel 3: dense FFN + LN2 + mask, 16 nodes per CTA (grid 256), bf16 MMA.
// dense1: warp w owns cols w*64..w*64+63. dense2: warp w owns cols w*16..+15.
// ---------------------------------------------------------------------------
__global__ void __launch_bounds__(256, 2)
dense_kernel(const float* __restrict__ maskV_g,
             const float* __restrict__ bd1, const float* __restrict__ bd2,
             const float* __restrict__ g2, const float* __restrict__ be2,
             float* __restrict__ out)
{
    extern __shared__ float smf[];
    uint32_t* smu = (uint32_t*)smf;
    uint32_t* hsb = smu + DM_HSB;
    uint32_t* d1b = smu + DM_D1B;
    float* hsf = smf + DM_HSF;
    float* x2s = smf + DM_X2;

    int node0 = blockIdx.x * 16;
    int t = threadIdx.x;
    int w = t >> 5, lane = t & 31;
    int gid = lane >> 2, q = lane & 3;

    // stage hs: fp32 copy + bf16 pack (16 rows x 128)
    {
        const float2* src = (const float2*)(g_hs + (size_t)node0*HH);
        #pragma unroll
        for (int i = t; i < 1024; i += 256) {
            float2 v = src[i];
            int row = i >> 6, cp = i & 63;
            hsf[row*128 + cp*2]     = v.x;
            hsf[row*128 + cp*2 + 1] = v.y;
            hsb[row*AST + cp] = pkbf(v.x, v.y);
        }
    }
    __syncthreads();

    const uint32_t* a_r0 = hsb + gid*AST + q;
    const uint32_t* a_r1 = a_r0 + 8*AST;

    // ---------------- dense1: 128 -> 512, relu, bf16 out ----------------
    {
        float acc[8][4];
        #pragma unroll
        for (int nt = 0; nt < 8; ++nt)
            #pragma unroll
            for (int i = 0; i < 4; ++i) acc[nt][i] = 0.f;
        mma_blk<8>(acc, a_r0, a_r1, g_wd1_b + w*(8*128) + lane);
        #pragma unroll
        for (int nt = 0; nt < 8; ++nt) {
            int cb = w*64 + nt*8 + 2*q;
            float ba = bd1[cb], bb = bd1[cb+1];
            d1b[gid*D1ST + (cb>>1)] =
                pkbf(fmaxf(acc[nt][0] + ba, 0.f), fmaxf(acc[nt][1] + bb, 0.f));
            d1b[(gid+8)*D1ST + (cb>>1)] =
                pkbf(fmaxf(acc[nt][2] + ba, 0.f), fmaxf(acc[nt][3] + bb, 0.f));
        }
    }
    __syncthreads();

    // ---------------- dense2: 512 -> 128, + bd2 + residual ----------------
    {
        float acc[2][4];
        #pragma unroll
        for (int nt = 0; nt < 2; ++nt)
            #pragma unroll
            for (int i = 0; i < 4; ++i) acc[nt][i] = 0.f;
        const uint32_t* d_r0 = d1b + gid*D1ST + q;
        const uint32_t* d_r1 = d_r0 + 8*D1ST;
        int ng2 = w >> 2, nth2 = w & 3;
        const uint4* frag = g_wd2_b + ng2*(32*128) + lane;
        #pragma unroll 8
        for (int ks = 0; ks < 32; ++ks) {
            uint32_t a0 = d_r0[ks*8], a1 = d_r1[ks*8], a2 = d_r0[ks*8+4], a3 = d_r1[ks*8+4];
            uint4 b = frag[ks*128 + nth2*32];
            mma16816(acc[0], a0, a1, a2, a3, b.x, b.y);
            mma16816(acc[1], a0, a1, a2, a3, b.z, b.w);
        }
        int r0 = gid, r1 = gid + 8;
        #pragma unroll
        for (int nt = 0; nt < 2; ++nt) {
            int cb = ng2*64 + nth2*16 + nt*8 + 2*q;
            float ba = bd2[cb], bb = bd2[cb+1];
            x2s[r0*128 + cb]     = acc[nt][0] + ba + hsf[r0*128 + cb];
            x2s[r0*128 + cb + 1] = acc[nt][1] + bb + hsf[r0*128 + cb + 1];
            x2s[r1*128 + cb]     = acc[nt][2] + ba + hsf[r1*128 + cb];
            x2s[r1*128 + cb + 1] = acc[nt][3] + bb + hsf[r1*128 + cb + 1];
        }
    }
    __syncthreads();

    // ---------------- LN2 + mask: warp w handles nodes w*2, w*2+1 ----------
    #pragma unroll
    for (int nn = 0; nn < 2; ++nn) {
        int row = w*2 + nn;
        float v0 = x2s[row*128 + lane];
        float v1 = x2s[row*128 + lane + 32];
        float v2 = x2s[row*128 + lane + 64];
        float v3 = x2s[row*128 + lane + 96];
        float mu = warp_sum(v0+v1+v2+v3) * (1.0f/HH);
        float d0 = v0-mu, d1 = v1-mu, d2 = v2-mu, d3 = v3-mu;
        float var = warp_sum(d0*d0+d1*d1+d2*d2+d3*d3) * (1.0f/HH);
        float rs = rsqrtf(var + 1e-5f);
        float mk = maskV_g[node0 + row];
        float* o = out + (size_t)(node0 + row)*HH;
        o[lane]      = (d0*rs*g2[lane]      + be2[lane])      * mk;
        o[lane + 32] = (d1*rs*g2[lane + 32] + be2[lane + 32]) * mk;
        o[lane + 64] = (d2*rs*g2[lane + 64] + be2[lane + 64]) * mk;
        o[lane + 96] = (d3*rs*g2[lane + 96] + be2[lane + 96]) * mk;
    }
}

// ---------------------------------------------------------------------------
extern "C" void kernel_launch(void* const* d_in, const int* in_sizes, int n_in,
                              void* d_out, int out_size)
{
    const float* hV    = (const float*)d_in[0];
    const float* hE    = (const float*)d_in[1];
    const float* X     = (const float*)d_in[2];
    const float* maskV = (const float*)d_in[3];
    const float* maskA = (const float*)d_in[4];
    const float* Wp    = (const float*)d_in[5];
    const float* bp    = (const float*)d_in[6];
    const float* Wm1   = (const float*)d_in[7];
    const float* bm1   = (const float*)d_in[8];
    const float* Wm2   = (const float*)d_in[9];
    const float* bm2   = (const float*)d_in[10];
    const float* Wm3   = (const float*)d_in[11];
    const float* bm3   = (const float*)d_in[12];
    const float* g1    = (const float*)d_in[13];
    const float* be1   = (const float*)d_in[14];
    const float* Wd1   = (const float*)d_in[15];
    const float* bd1   = (const float*)d_in[16];
    const float* Wd2   = (const float*)d_in[17];
    const float* bd2   = (const float*)d_in[18];
    const float* g2    = (const float*)d_in[19];
    const float* be2   = (const float*)d_in[20];
    const int*   Eidx  = (const int*)d_in[21];
    float* out = (float*)d_out;

    cudaFuncSetAttribute(msg_kernel, cudaFuncAttributeMaxDynamicSharedMemorySize, SMEM_BYTES);
    cudaFuncSetAttribute(dense_kernel, cudaFuncAttributeMaxDynamicSharedMemorySize, DSMEM_BYTES);

    long long hcount = (long long)NODES * HH;
    long long availE = (long long)out_size - hcount;
    if (availE < 0) availE = 0;
    long long emax = (long long)BB*NN*KK*DD;
    if (availE > emax) availE = emax;

    node_prep_kernel<<<NODES/NPB + 64, 128>>>(hV, X, Wp, bp, Wm1,
                                              Wm2, Wm3, Wd1, Wd2);
    s1_kernel<<<NODES/64, 256>>>(bm1);
    msg_kernel<<<NODES/2, 256, SMEM_BYTES>>>(hV, hE, maskA, bm2, bm3,
                                             g1, be1, Eidx,
                                             out + hcount, availE);
    dense_kernel<<<NODES/16, 256, DSMEM_BYTES>>>(maskV, bd1, bd2, g2, be2, out);
}

// round 15
// speedup vs baseline: 1.1883x; 1.1534x over previous
#include <cuda_runtime.h>
#include <cuda_bf16.h>
#include <math.h>
#include <stdint.h>

#define BB 8
#define NN 512
#define KK 32
#define DD 128
#define HH 128
#define PP 8
#define NODES (BB*NN)

// Scratch (allocation-free rule: __device__ globals)
__device__ float g_pg[NODES*PP*3];
__device__ float g_R[NODES*9];
__device__ float g_t[NODES*3];
__device__ float g_s1[NODES*HH];        // static layer-1 pre-activation (incl bias)
__device__ float g_hs[NODES*HH];        // post-LN1 hidden state
__device__ uint32_t g_sA[NODES*80];     // bf16-packed static A rows: hv(64)|pl(12)|pln(4) u32

// fragment-packed bf16 weights: [ng][ks][nth][lane] -> uint4(b0a,b1a,b0b,b1b)
__device__ uint4 g_w1e_b[2*16*4*32];   // Wm1 rows 128..383 (K=256, KS=16)
__device__ uint4 g_w1g_b[2*3*4*32];    // Wm1 rows 416..455 (K=40->48, KS=3)
__device__ uint4 g_ws_b[2*10*4*32];    // Wm1 static rows (K=160, KS=10; row map k<128?k:k+256)
__device__ uint4 g_w2_b[2*8*4*32];     // Wm2 (K=128, KS=8)
__device__ uint4 g_w3_b[2*8*4*32];     // Wm3
__device__ uint4 g_wd1_b[8*8*4*32];    // Wd1 (K=128, N=512: 8 n-groups, KS=8)
__device__ uint4 g_wd2_b[2*32*4*32];   // Wd2 (K=512, N=128: KS=32)

__device__ __forceinline__ uint32_t pkbf(float a, float b) {
    __nv_bfloat162 h = __floats2bfloat162_rn(a, b);
    return *reinterpret_cast<uint32_t*>(&h);
}

// ---------------------------------------------------------------------------
// weight packing helper (bf16 mma-fragment order)
// ---------------------------------------------------------------------------
__device__ __forceinline__ uint4 packb(const float* __restrict__ W, int ld,
                                       int Krows, int i, int KS)
{
    int lane = i & 31;
    int nth  = (i >> 5) & 3;
    int rest = i >> 7;
    int ks = rest % KS;
    int ng = rest / KS;
    int q = lane & 3;
    int gid = lane >> 2;
    int k0 = ks * 16;
    int na = ng*64 + nth*16 + gid;
    auto f = [&](int k, int n) -> float {
        return (k < Krows) ? W[(size_t)k*ld + n] : 0.f;
    };
    uint4 o;
    o.x = pkbf(f(k0+2*q,   na),   f(k0+2*q+1, na));
    o.y = pkbf(f(k0+2*q+8, na),   f(k0+2*q+9, na));
    o.z = pkbf(f(k0+2*q,   na+8), f(k0+2*q+1, na+8));
    o.w = pkbf(f(k0+2*q+8, na+8), f(k0+2*q+9, na+8));
    return o;
}

// static-row variant: K=160 rows of Wm1 with row map k<128 ? k : k+256
__device__ __forceinline__ uint4 packs(const float* __restrict__ Wm1, int i)
{
    int lane = i & 31;
    int nth  = (i >> 5) & 3;
    int rest = i >> 7;
    int ks = rest % 10;
    int ng = rest / 10;
    int q = lane & 3;
    int gid = lane >> 2;
    int k0 = ks * 16;
    int na = ng*64 + nth*16 + gid;
    auto f = [&](int k, int n) -> float {
        int r = (k < 128) ? k : k + 256;
        return Wm1[(size_t)r*128 + n];
    };
    uint4 o;
    o.x = pkbf(f(k0+2*q,   na),   f(k0+2*q+1, na));
    o.y = pkbf(f(k0+2*q+8, na),   f(k0+2*q+9, na));
    o.z = pkbf(f(k0+2*q,   na+8), f(k0+2*q+1, na+8));
    o.w = pkbf(f(k0+2*q+8, na+8), f(k0+2*q+9, na+8));
    return o;
}

// ---------------------------------------------------------------------------
// Kernel 1: blocks [0, NODES/NPB): frames + points + packed static A rows,
//           NPB nodes/CTA. blocks [NODES/NPB, +64): weight packing.
// ---------------------------------------------------------------------------
#define NPB 4
__global__ void node_prep_kernel(const float* __restrict__ hV_g,
                                 const float* __restrict__ X,
                                 const float* __restrict__ Wp,
                                 const float* __restrict__ bp,
                                 const float* __restrict__ Wm1,
                                 const float* __restrict__ Wm2,
                                 const float* __restrict__ Wm3,
                                 const float* __restrict__ Wd1,
                                 const float* __restrict__ Wd2)
{
    int t = threadIdx.x;
    if (blockIdx.x >= NODES/NPB) {
        // ---- weight packing blocks ----
        int i = (blockIdx.x - NODES/NPB) * 128 + t;   // 0..8191
        if (i < 2*16*4*32) g_w1e_b[i] = packb(Wm1 + 128*128, 128, 256, i, 16);
        if (i < 2*8*4*32) {
            g_w2_b[i] = packb(Wm2, 128, 128, i, 8);
            g_w3_b[i] = packb(Wm3, 128, 128, i, 8);
        }
        if (i < 2*3*4*32)  g_w1g_b[i] = packb(Wm1 + 416*128, 128, 40, i, 3);
        if (i < 2*10*4*32) g_ws_b[i] = packs(Wm1, i);
        if (i < 8*8*4*32)  g_wd1_b[i] = packb(Wd1, 512, 128, i, 8);
        if (i < 2*32*4*32) g_wd2_b[i] = packb(Wd2, 128, 512, i, 32);
        return;
    }

    int node0 = blockIdx.x * NPB;
    __shared__ float hvS[NPB*128];
    __shared__ float plS[NPB*24];
    __shared__ float plnS[NPB*8];
    __shared__ float RnS[NPB*9];
    __shared__ float tnS[NPB*3];

    #pragma unroll
    for (int nn = 0; nn < NPB; ++nn)
        hvS[nn*128 + t] = hV_g[(size_t)(node0+nn)*DD + t];
    __syncthreads();

    if (t < NPB*24) {
        int nn = t / 24, j = t % 24;
        float acc = bp[j];
        #pragma unroll 8
        for (int d = 0; d < DD; ++d) acc += hvS[nn*128 + d] * Wp[d*24 + j];
        plS[nn*24 + j] = acc;
    } else if (t < NPB*24 + NPB) {
        int nn = t - NPB*24;
        const float* x = X + (size_t)(node0+nn)*9;
        float Xn0=x[0],Xn1=x[1],Xn2=x[2];
        float Xa0=x[3],Xa1=x[4],Xa2=x[5];
        float Xc0=x[6],Xc1=x[7],Xc2=x[8];
        float v10=Xc0-Xa0, v11=Xc1-Xa1, v12=Xc2-Xa2;
        float v20=Xn0-Xa0, v21=Xn1-Xa1, v22=Xn2-Xa2;
        float inv1 = rsqrtf(v10*v10+v11*v11+v12*v12+1e-8f);
        float e10=v10*inv1, e11=v11*inv1, e12=v12*inv1;
        float dp = e10*v20+e11*v21+e12*v22;
        float u20=v20-e10*dp, u21=v21-e11*dp, u22=v22-e12*dp;
        float inv2 = rsqrtf(u20*u20+u21*u21+u22*u22+1e-8f);
        float e20=u20*inv2, e21=u21*inv2, e22=u22*inv2;
        float e30=e11*e22-e12*e21;
        float e31=e12*e20-e10*e22;
        float e32=e10*e21-e11*e20;
        float* Rn = RnS + nn*9;
        Rn[0]=e10; Rn[1]=e20; Rn[2]=e30;
        Rn[3]=e11; Rn[4]=e21; Rn[5]=e31;
        Rn[6]=e12; Rn[7]=e22; Rn[8]=e32;
        tnS[nn*3+0]=Xa0*0.1f; tnS[nn*3+1]=Xa1*0.1f; tnS[nn*3+2]=Xa2*0.1f;
    }
    __syncthreads();

    if (t < NPB*8) {
        int nn = t >> 3, p = t & 7;
        float a=plS[nn*24+p*3+0], b=plS[nn*24+p*3+1], c=plS[nn*24+p*3+2];
        plnS[nn*8+p] = sqrtf(a*a+b*b+c*c + 1e-8f);
    }
    __syncthreads();

    if (t < NPB*24) {
        int nn = t / 24, j = t % 24;
        int p = j/3, i = j%3;
        const float* Rn = RnS + nn*9;
        float pg = tnS[nn*3+i] + Rn[i*3+0]*plS[nn*24+p*3+0]
                 + Rn[i*3+1]*plS[nn*24+p*3+1] + Rn[i*3+2]*plS[nn*24+p*3+2];
        g_pg[(size_t)(node0+nn)*24 + t] = pg;
    }
    if (t < NPB*9) g_R[(size_t)node0*9 + t] = RnS[t];
    if (t < NPB*3) g_t[(size_t)node0*3 + t] = tnS[t];

    // packed static A rows: hv pairs (64 u32), pl pairs (12), pln pairs (4)
    for (int idx = t; idx < NPB*80; idx += 128) {
        int nn = idx / 80, c = idx % 80;
        uint32_t v;
        if (c < 64)      v = pkbf(hvS[nn*128 + 2*c],       hvS[nn*128 + 2*c + 1]);
        else if (c < 76) { int j = (c-64)*2; v = pkbf(plS[nn*24 + j], plS[nn*24 + j + 1]); }
        else             { int p = (c-76)*2; v = pkbf(plnS[nn*8 + p], plnS[nn*8 + p + 1]); }
        g_sA[(size_t)(node0+nn)*80 + c] = v;
    }
}

// ---------------------------------------------------------------------------
// bf16 m16n8k16 mma helpers
// ---------------------------------------------------------------------------
__device__ __forceinline__ void mma16816(float (&d)[4],
                                         uint32_t a0, uint32_t a1,
                                         uint32_t a2, uint32_t a3,
                                         uint32_t b0, uint32_t b1)
{
    asm volatile(
        "mma.sync.aligned.m16n8k16.row.col.f32.bf16.bf16.f32 "
        "{%0,%1,%2,%3},{%4,%5,%6,%7},{%8,%9},{%0,%1,%2,%3};"
        : "+f"(d[0]), "+f"(d[1]), "+f"(d[2]), "+f"(d[3])
        : "r"(a0), "r"(a1), "r"(a2), "r"(a3), "r"(b0), "r"(b1));
}

template<int KSTEPS>
__device__ __forceinline__ void mma_blk(float (*acc)[4],
                                        const uint32_t* r0, const uint32_t* r1,
                                        const uint4* __restrict__ frag)
{
    #pragma unroll
    for (int ks = 0; ks < KSTEPS; ++ks) {
        uint32_t a0 = r0[ks*8], a1 = r1[ks*8], a2 = r0[ks*8+4], a3 = r1[ks*8+4];
        const uint4* fb = frag + ks*128;
        #pragma unroll
        for (int nth = 0; nth < 4; ++nth) {
            uint4 b = fb[nth*32];
            mma16816(acc[2*nth],   a0, a1, a2, a3, b.x, b.y);
            mma16816(acc[2*nth+1], a0, a1, a2, a3, b.z, b.w);
        }
    }
}

// 2-mtile variant: warp covers 32 edges (rows r0/r1 and r2/r3) x 32 cols.
// frag covers a 64-col packed group; sub in {0,1} selects which 32-col half.
// acc[0..3] = m-tile0 n-tiles, acc[4..7] = m-tile1 n-tiles.
template<int KSTEPS>
__device__ __forceinline__ void mma_blk2(float (*acc)[4],
                                         const uint32_t* r0, const uint32_t* r1,
                                         const uint32_t* r2, const uint32_t* r3,
                                         const uint4* __restrict__ frag, int sub)
{
    #pragma unroll
    for (int ks = 0; ks < KSTEPS; ++ks) {
        uint32_t a0 = r0[ks*8], a1 = r1[ks*8], a2 = r0[ks*8+4], a3 = r1[ks*8+4];
        uint32_t c0 = r2[ks*8], c1 = r3[ks*8], c2 = r2[ks*8+4], c3 = r3[ks*8+4];
        const uint4* fb = frag + ks*128;
        uint4 b0 = fb[(sub*2+0)*32];
        uint4 b1 = fb[(sub*2+1)*32];
        mma16816(acc[0], a0,a1,a2,a3, b0.x, b0.y);
        mma16816(acc[1], a0,a1,a2,a3, b0.z, b0.w);
        mma16816(acc[2], a0,a1,a2,a3, b1.x, b1.y);
        mma16816(acc[3], a0,a1,a2,a3, b1.z, b1.w);
        mma16816(acc[4], c0,c1,c2,c3, b0.x, b0.y);
        mma16816(acc[5], c0,c1,c2,c3, b0.z, b0.w);
        mma16816(acc[6], c0,c1,c2,c3, b1.x, b1.y);
        mma16816(acc[7], c0,c1,c2,c3, b1.z, b1.w);
    }
}

__device__ __forceinline__ float warp_sum(float v) {
    #pragma unroll
    for (int o = 16; o; o >>= 1) v += __shfl_xor_sync(0xffffffffu, v, o);
    return v;
}

// ---------------------------------------------------------------------------
// Kernel 1b: s1 = staticA @ Ws + bm1 via bf16 MMA, 64 nodes/CTA (grid 64)
// ---------------------------------------------------------------------------
#define SAST 84
__global__ void __launch_bounds__(256, 2)
s1_kernel(const float* __restrict__ bm1)
{
    __shared__ uint32_t sA[64*SAST];

    int node0 = blockIdx.x * 64;
    int t = threadIdx.x;
    int w = t >> 5, lane = t & 31;
    int mh = w & 3, ng = w >> 2;
    int gid = lane >> 2, q = lane & 3;

    {
        const uint4* src = (const uint4*)(g_sA + (size_t)node0*80);
        #pragma unroll
        for (int i = t; i < 64*20; i += 256) {
            int node = i / 20, c = i % 20;
            *(uint4*)(sA + node*SAST + c*4) = src[i];
        }
    }
    __syncthreads();

    float acc[8][4];
    #pragma unroll
    for (int nt = 0; nt < 8; ++nt)
        #pragma unroll
        for (int i = 0; i < 4; ++i) acc[nt][i] = 0.f;

    const uint32_t* r0 = sA + (mh*16 + gid)*SAST + q;
    const uint32_t* r1 = r0 + 8*SAST;
    mma_blk<10>(acc, r0, r1, g_ws_b + ng*(10*128) + lane);

    int r0i = mh*16 + gid, r1i = r0i + 8;
    #pragma unroll
    for (int nt = 0; nt < 8; ++nt) {
        int cb = ng*64 + nt*8 + 2*q;
        float ba = bm1[cb], bb = bm1[cb+1];
        g_s1[(size_t)(node0+r0i)*HH + cb]     = acc[nt][0] + ba;
        g_s1[(size_t)(node0+r0i)*HH + cb + 1] = acc[nt][1] + bb;
        g_s1[(size_t)(node0+r1i)*HH + cb]     = acc[nt][2] + ba;
        g_s1[(size_t)(node0+r1i)*HH + cb + 1] = acc[nt][3] + bb;
    }
}

// msg_kernel smem layout (u32 units)
#define AST 68          // 64 data u32 (128 bf16) + 4 pad
#define GST 28          // 24 data u32 (48 bf16) + 4 pad
#define SM_BUFA  0      // 64*68 = 4352 : h_E -> relu(L1)
#define SM_BUFB  4352   // nbr_hV -> relu(L2)
#define SM_GEO   8704   // 64*28 = 1792
#define SM_HV    10496  // 256 (fp32)
#define SM_S1    10752  // 256
#define SM_RN    11008  // 24
#define SM_TN    11032  // 8
#define SM_PGN   11040  // 48
#define SM_MA    11088  // 64
#define SM_RED   11152  // 16
#define SM_PD    11168  // 256
#define SM_EIX   11424  // 64
#define SM_U32   11488
#define SMEM_BYTES (SM_U32*4)

// ---------------------------------------------------------------------------
// Kernel 2: 2 nodes per CTA, bf16 MMA message MLP, ends at LN1 -> g_hs.
// 8 warps: mh2 = w&1 (node / 32-edge group), ng4 = w>>1 (32-col group).
// ---------------------------------------------------------------------------
__global__ void __launch_bounds__(256, 3)
msg_kernel(const float* __restrict__ hV_g, const float* __restrict__ hE_g,
           const float* __restrict__ maskA_g,
           const float* __restrict__ bm2, const float* __restrict__ bm3,
           const float* __restrict__ g1, const float* __restrict__ be1,
           const int* __restrict__ Eidx,
           float* __restrict__ outE, long long availE)
{
    extern __shared__ float smf[];
    uint32_t* smu = (uint32_t*)smf;
    uint32_t* bufA = smu + SM_BUFA;
    uint32_t* bufB = smu + SM_BUFB;
    uint32_t* geoU = smu + SM_GEO;
    float* hv  = smf + SM_HV;
    float* s1  = smf + SM_S1;
    float* Rn  = smf + SM_RN;
    float* tn  = smf + SM_TN;
    float* pgn = smf + SM_PGN;
    float* mA  = smf + SM_MA;
    float* red = smf + SM_RED;
    float* pd  = smf + SM_PD;
    int*   eix = (int*)(smu + SM_EIX);

    int node0 = blockIdx.x * 2;
    int batch = node0 / NN;
    int t = threadIdx.x;
    int w = t >> 5, lane = t & 31;
    int mh2 = w & 1, ng4 = w >> 1;
    int gid = lane >> 2, q = lane & 3;

    hv[t] = hV_g[(size_t)node0*DD + t];
    s1[t] = g_s1[(size_t)node0*HH + t];
    if (t < 48) pgn[t] = g_pg[(size_t)node0*24 + t];
    else if (t < 66) Rn[t-48] = g_R[(size_t)node0*9 + (t-48)];
    else if (t < 72) tn[t-66] = g_t[(size_t)node0*3 + (t-66)];
    if (t >= 128 && t < 192) mA[t-128] = maskA_g[(size_t)node0*KK + (t-128)];
    else if (t >= 192) eix[t-192] = Eidx[(size_t)node0*KK + (t-192)];
    __syncthreads();

    // ============ fused staging: h_E->bufA (+passthrough), nbr->bufB, geo ==
    {
        long long ebase = (long long)node0 * KK * DD;
        const float4* src = (const float4*)(hE_g + ebase);
        float4* dst = (float4*)(outE + ebase);
        bool full = (ebase + 2*KK*DD) <= availE;
        #pragma unroll
        for (int i = 0; i < 8; ++i) {
            int f4 = t + i*256;          // 0..2047
            float4 v = src[f4];
            if (full || (ebase + (long long)f4*4 + 4) <= availE) dst[f4] = v;
            int e = f4 >> 5, cp = (f4 & 31) * 2;
            uint2 o;
            o.x = pkbf(v.x, v.y);
            o.y = pkbf(v.z, v.w);
            *(uint2*)(bufA + e*AST + cp) = o;
        }
    }
    // nbr_hV gather -> bufB
    #pragma unroll
    for (int ii = 0; ii < 8; ++ii) {
        int e = w + ii*8;
        int j = eix[e];
        const float4* src = (const float4*)(hV_g + (size_t)(batch*NN + j)*DD);
        float4 v = src[lane];
        uint2 o;
        o.x = pkbf(v.x, v.y);
        o.y = pkbf(v.z, v.w);
        *(uint2*)(bufB + e*AST + lane*2) = o;
    }
    // geometry rows
    #pragma unroll
    for (int ii = 0; ii < 8; ++ii) {
        int e = w + ii*8;
        if (lane < 8) {
            int p = lane;
            int nn = e >> 5;
            int j = eix[e];
            const float* qg = g_pg + (size_t)(batch*NN + j)*24 + p*3;
            float q0 = qg[0], q1 = qg[1], q2 = qg[2];
            const float* R = Rn + nn*9;
            float d0 = pgn[nn*24+p*3+0]-q0, d1 = pgn[nn*24+p*3+1]-q1, d2 = pgn[nn*24+p*3+2]-q2;
            float cc0 = q0 - tn[nn*3+0], cc1 = q1 - tn[nn*3+1], cc2 = q2 - tn[nn*3+2];
            float l0 = R[0]*cc0 + R[3]*cc1 + R[6]*cc2;
            float l1 = R[1]*cc0 + R[4]*cc1 + R[7]*cc2;
            float l2 = R[2]*cc0 + R[5]*cc1 + R[8]*cc2;
            __nv_bfloat16* row = (__nv_bfloat16*)(geoU + e*GST);
            row[p*3+0] = __float2bfloat16_rn(l0);
            row[p*3+1] = __float2bfloat16_rn(l1);
            row[p*3+2] = __float2bfloat16_rn(l2);
            row[24+p] = __float2bfloat16_rn(sqrtf(l0*l0+l1*l1+l2*l2 + 1e-8f));
            row[32+p] = __float2bfloat16_rn(sqrtf(d0*d0+d1*d1+d2*d2 + 1e-8f));
            if (p == 0) {
                uint32_t* ru = geoU + e*GST;
                ru[20] = 0u; ru[21] = 0u; ru[22] = 0u; ru[23] = 0u;
            }
        }
    }
    __syncthreads();

    int rowB = mh2*32 + gid;
    const uint32_t* a_r0 = bufA + rowB*AST + q;
    const uint32_t* a_r1 = a_r0 + 8*AST;
    const uint32_t* a_r2 = a_r0 + 16*AST;
    const uint32_t* a_r3 = a_r0 + 24*AST;
    const uint32_t* b_r0 = bufB + rowB*AST + q;
    const uint32_t* b_r1 = b_r0 + 8*AST;
    const uint32_t* b_r2 = b_r0 + 16*AST;
    const uint32_t* b_r3 = b_r0 + 24*AST;
    int ngp = ng4 >> 1, sub = ng4 & 1;

    // ============ layer 1: A (h_E) + B (nbr) + geo, back-to-back ============
    float acc[8][4];
    #pragma unroll
    for (int nt = 0; nt < 8; ++nt)
        #pragma unroll
        for (int i = 0; i < 4; ++i) acc[nt][i] = 0.f;

    mma_blk2<8>(acc, a_r0, a_r1, a_r2, a_r3, g_w1e_b + ngp*(16*128) + lane, sub);
    mma_blk2<8>(acc, b_r0, b_r1, b_r2, b_r3, g_w1e_b + ngp*(16*128) + 8*128 + lane, sub);
    {
        const uint32_t* g_r0 = geoU + rowB*GST + q;
        mma_blk2<3>(acc, g_r0, g_r0 + 8*GST, g_r0 + 16*GST, g_r0 + 24*GST,
                    g_w1g_b + ngp*(3*128) + lane, sub);
    }
    __syncthreads();   // all reads of bufA / bufB complete

    // add static part + relu, store bf16 to bufA (h_E dead)
    {
        const float* s1n = s1 + mh2*128;
        #pragma unroll
        for (int nt = 0; nt < 4; ++nt) {
            int cb = ng4*32 + nt*8 + 2*q;
            float sa = s1n[cb], sb = s1n[cb+1];
            int cp = cb >> 1;
            bufA[rowB*AST + cp] =
                pkbf(fmaxf(acc[nt][0] + sa, 0.f), fmaxf(acc[nt][1] + sb, 0.f));
            bufA[(rowB+8)*AST + cp] =
                pkbf(fmaxf(acc[nt][2] + sa, 0.f), fmaxf(acc[nt][3] + sb, 0.f));
            bufA[(rowB+16)*AST + cp] =
                pkbf(fmaxf(acc[4+nt][0] + sa, 0.f), fmaxf(acc[4+nt][1] + sb, 0.f));
            bufA[(rowB+24)*AST + cp] =
                pkbf(fmaxf(acc[4+nt][2] + sa, 0.f), fmaxf(acc[4+nt][3] + sb, 0.f));
        }
    }
    __syncthreads();

    // ============ layer 2 (reads bufA, writes bufB) ========================
    #pragma unroll
    for (int nt = 0; nt < 8; ++nt)
        #pragma unroll
        for (int i = 0; i < 4; ++i) acc[nt][i] = 0.f;
    mma_blk2<8>(acc, a_r0, a_r1, a_r2, a_r3, g_w2_b + ngp*(8*128) + lane, sub);
    __syncthreads();   // scheduling fence: keeps bufB store after all L2 reads
    {
        #pragma unroll
        for (int nt = 0; nt < 4; ++nt) {
            int cb = ng4*32 + nt*8 + 2*q;
            float ba = bm2[cb], bb = bm2[cb+1];
            int cp = cb >> 1;
            bufB[rowB*AST + cp] =
                pkbf(fmaxf(acc[nt][0] + ba, 0.f), fmaxf(acc[nt][1] + bb, 0.f));
            bufB[(rowB+8)*AST + cp] =
                pkbf(fmaxf(acc[nt][2] + ba, 0.f), fmaxf(acc[nt][3] + bb, 0.f));
            bufB[(rowB+16)*AST + cp] =
                pkbf(fmaxf(acc[4+nt][0] + ba, 0.f), fmaxf(acc[4+nt][1] + bb, 0.f));
            bufB[(rowB+24)*AST + cp] =
                pkbf(fmaxf(acc[4+nt][2] + ba, 0.f), fmaxf(acc[4+nt][3] + bb, 0.f));
        }
    }
    __syncthreads();

    // ============ layer 3 (reads bufB) + masked full per-warp mean =========
    #pragma unroll
    for (int nt = 0; nt < 8; ++nt)
        #pragma unroll
        for (int i = 0; i < 4; ++i) acc[nt][i] = 0.f;
    mma_blk2<8>(acc, b_r0, b_r1, b_r2, b_r3, g_w3_b + ngp*(8*128) + lane, sub);
    {
        float mk0 = mA[mh2*32 + gid];
        float mk1 = mA[mh2*32 + gid + 8];
        float mk2 = mA[mh2*32 + gid + 16];
        float mk3 = mA[mh2*32 + gid + 24];
        #pragma unroll
        for (int nt = 0; nt < 4; ++nt) {
            int cb = ng4*32 + nt*8 + 2*q;
            float ba = bm3[cb], bb = bm3[cb+1];
            float ve = (acc[nt][0] + ba)*mk0 + (acc[nt][2] + ba)*mk1
                     + (acc[4+nt][0] + ba)*mk2 + (acc[4+nt][2] + ba)*mk3;
            float vo = (acc[nt][1] + bb)*mk0 + (acc[nt][3] + bb)*mk1
                     + (acc[4+nt][1] + bb)*mk2 + (acc[4+nt][3] + bb)*mk3;
            #pragma unroll
            for (int o = 4; o <= 16; o <<= 1) {
                ve += __shfl_xor_sync(0xffffffffu, ve, o);
                vo += __shfl_xor_sync(0xffffffffu, vo, o);
            }
            if (gid == 0) {
                pd[mh2*128 + cb] = ve;
                pd[mh2*128 + cb + 1] = vo;
            }
        }
    }
    __syncthreads();

    // ---------------- LN1 for both nodes -> g_hs ----------------
    int nodeL = t >> 7, c = t & 127;
    float x, dx;
    {
        float nm = pd[nodeL*128 + c] * (1.0f/KK);
        x = hv[nodeL*128 + c] + nm;
        float sA = warp_sum(x);
        if (!lane) red[w] = sA;
    }
    __syncthreads();
    {
        float mu = (red[nodeL*4+0]+red[nodeL*4+1]+red[nodeL*4+2]+red[nodeL*4+3]) * (1.0f/HH);
        dx = x - mu;
        float sB = warp_sum(dx*dx);
        __syncwarp();
        if (!lane) red[8+w] = sB;
    }
    __syncthreads();
    {
        float var = (red[8+nodeL*4]+red[9+nodeL*4]+red[10+nodeL*4]+red[11+nodeL*4]) * (1.0f/HH);
        g_hs[(size_t)(node0+nodeL)*HH + c] = dx * rsqrtf(var + 1e-5f) * g1[c] + be1[c];
    }
}

// dense kernel smem layout (u32 units), 16 nodes / CTA
#define D1ST 260       // 256 data u32 (512 bf16) + 4 pad
#define DM_HSB 0       // 16*68 = 1088
#define DM_D1B 1088    // 16*260 = 4160
#define DM_HSF 5248    // 2048 (fp32)
#define DM_X2  7296    // 2048 (fp32)
#define DM_U32 9344
#define DSMEM_BYTES (DM_U32*4)

// ---------------------------------------------------------------------------
// Kernel 3: dense FFN + LN2 + mask, 16 nodes per CTA (grid 256), bf16 MMA.
// ---------------------------------------------------------------------------
__global__ void __launch_bounds__(256, 2)
dense_kernel(const float* __restrict__ maskV_g,
             const float* __restrict__ bd1, const float* __restrict__ bd2,
             const float* __restrict__ g2, const float* __restrict__ be2,
             float* __restrict__ out)
{
    extern __shared__ float smf[];
    uint32_t* smu = (uint32_t*)smf;
    uint32_t* hsb = smu + DM_HSB;
    uint32_t* d1b = smu + DM_D1B;
    float* hsf = smf + DM_HSF;
    float* x2s = smf + DM_X2;

    int node0 = blockIdx.x * 16;
    int t = threadIdx.x;
    int w = t >> 5, lane = t & 31;
    int gid = lane >> 2, q = lane & 3;

    // stage hs: fp32 copy + bf16 pack (16 rows x 128)
    {
        const float2* src = (const float2*)(g_hs + (size_t)node0*HH);
        #pragma unroll
        for (int i = t; i < 1024; i += 256) {
            float2 v = src[i];
            int row = i >> 6, cp = i & 63;
            hsf[row*128 + cp*2]     = v.x;
            hsf[row*128 + cp*2 + 1] = v.y;
            hsb[row*AST + cp] = pkbf(v.x, v.y);
        }
    }
    __syncthreads();

    const uint32_t* a_r0 = hsb + gid*AST + q;
    const uint32_t* a_r1 = a_r0 + 8*AST;

    // ---------------- dense1: 128 -> 512, relu, bf16 out ----------------
    {
        float acc[8][4];
        #pragma unroll
        for (int nt = 0; nt < 8; ++nt)
            #pragma unroll
            for (int i = 0; i < 4; ++i) acc[nt][i] = 0.f;
        mma_blk<8>(acc, a_r0, a_r1, g_wd1_b + w*(8*128) + lane);
        #pragma unroll
        for (int nt = 0; nt < 8; ++nt) {
            int cb = w*64 + nt*8 + 2*q;
            float ba = bd1[cb], bb = bd1[cb+1];
            d1b[gid*D1ST + (cb>>1)] =
                pkbf(fmaxf(acc[nt][0] + ba, 0.f), fmaxf(acc[nt][1] + bb, 0.f));
            d1b[(gid+8)*D1ST + (cb>>1)] =
                pkbf(fmaxf(acc[nt][2] + ba, 0.f), fmaxf(acc[nt][3] + bb, 0.f));
        }
    }
    __syncthreads();

    // ---------------- dense2: 512 -> 128, + bd2 + residual ----------------
    {
        float acc[2][4];
        #pragma unroll
        for (int nt = 0; nt < 2; ++nt)
            #pragma unroll
            for (int i = 0; i < 4; ++i) acc[nt][i] = 0.f;
        const uint32_t* d_r0 = d1b + gid*D1ST + q;
        const uint32_t* d_r1 = d_r0 + 8*D1ST;
        int ng2 = w >> 2, nth2 = w & 3;
        const uint4* frag = g_wd2_b + ng2*(32*128) + lane;
        #pragma unroll 8
        for (int ks = 0; ks < 32; ++ks) {
            uint32_t a0 = d_r0[ks*8], a1 = d_r1[ks*8], a2 = d_r0[ks*8+4], a3 = d_r1[ks*8+4];
            uint4 b = frag[ks*128 + nth2*32];
            mma16816(acc[0], a0, a1, a2, a3, b.x, b.y);
            mma16816(acc[1], a0, a1, a2, a3, b.z, b.w);
        }
        int r0 = gid, r1 = gid + 8;
        #pragma unroll
        for (int nt = 0; nt < 2; ++nt) {
            int cb = ng2*64 + nth2*16 + nt*8 + 2*q;
            float ba = bd2[cb], bb = bd2[cb+1];
            x2s[r0*128 + cb]     = acc[nt][0] + ba + hsf[r0*128 + cb];
            x2s[r0*128 + cb + 1] = acc[nt][1] + bb + hsf[r0*128 + cb + 1];
            x2s[r1*128 + cb]     = acc[nt][2] + ba + hsf[r1*128 + cb];
            x2s[r1*128 + cb + 1] = acc[nt][3] + bb + hsf[r1*128 + cb + 1];
        }
    }
    __syncthreads();

    // ---------------- LN2 + mask: warp w handles nodes w*2, w*2+1 ----------
    #pragma unroll
    for (int nn = 0; nn < 2; ++nn) {
        int row = w*2 + nn;
        float v0 = x2s[row*128 + lane];
        float v1 = x2s[row*128 + lane + 32];
        float v2 = x2s[row*128 + lane + 64];
        float v3 = x2s[row*128 + lane + 96];
        float mu = warp_sum(v0+v1+v2+v3) * (1.0f/HH);
        float d0 = v0-mu, d1 = v1-mu, d2 = v2-mu, d3 = v3-mu;
        float var = warp_sum(d0*d0+d1*d1+d2*d2+d3*d3) * (1.0f/HH);
        float rs = rsqrtf(var + 1e-5f);
        float mk = maskV_g[node0 + row];
        float* o = out + (size_t)(node0 + row)*HH;
        o[lane]      = (d0*rs*g2[lane]      + be2[lane])      * mk;
        o[lane + 32] = (d1*rs*g2[lane + 32] + be2[lane + 32]) * mk;
        o[lane + 64] = (d2*rs*g2[lane + 64] + be2[lane + 64]) * mk;
        o[lane + 96] = (d3*rs*g2[lane + 96] + be2[lane + 96]) * mk;
    }
}

// ---------------------------------------------------------------------------
extern "C" void kernel_launch(void* const* d_in, const int* in_sizes, int n_in,
                              void* d_out, int out_size)
{
    const float* hV    = (const float*)d_in[0];
    const float* hE    = (const float*)d_in[1];
    const float* X     = (const float*)d_in[2];
    const float* maskV = (const float*)d_in[3];
    const float* maskA = (const float*)d_in[4];
    const float* Wp    = (const float*)d_in[5];
    const float* bp    = (const float*)d_in[6];
    const float* Wm1   = (const float*)d_in[7];
    const float* bm1   = (const float*)d_in[8];
    const float* Wm2   = (const float*)d_in[9];
    const float* bm2   = (const float*)d_in[10];
    const float* Wm3   = (const float*)d_in[11];
    const float* bm3   = (const float*)d_in[12];
    const float* g1    = (const float*)d_in[13];
    const float* be1   = (const float*)d_in[14];
    const float* Wd1   = (const float*)d_in[15];
    const float* bd1   = (const float*)d_in[16];
    const float* Wd2   = (const float*)d_in[17];
    const float* bd2   = (const float*)d_in[18];
    const float* g2    = (const float*)d_in[19];
    const float* be2   = (const float*)d_in[20];
    const int*   Eidx  = (const int*)d_in[21];
    float* out = (float*)d_out;

    cudaFuncSetAttribute(msg_kernel, cudaFuncAttributeMaxDynamicSharedMemorySize, SMEM_BYTES);
    cudaFuncSetAttribute(dense_kernel, cudaFuncAttributeMaxDynamicSharedMemorySize, DSMEM_BYTES);

    long long hcount = (long long)NODES * HH;
    long long availE = (long long)out_size - hcount;
    if (availE < 0) availE = 0;
    long long emax = (long long)BB*NN*KK*DD;
    if (availE > emax) availE = emax;

    node_prep_kernel<<<NODES/NPB + 64, 128>>>(hV, X, Wp, bp, Wm1,
                                              Wm2, Wm3, Wd1, Wd2);
    s1_kernel<<<NODES/64, 256>>>(bm1);
    msg_kernel<<<NODES/2, 256, SMEM_BYTES>>>(hV, hE, maskA, bm2, bm3,
                                             g1, be1, Eidx,
                                             out + hcount, availE);
    dense_kernel<<<NODES/16, 256, DSMEM_BYTES>>>(maskV, bd1, bd2, g2, be2, out);
}

// round 16
// speedup vs baseline: 1.1916x; 1.0028x over previous
#include <cuda_runtime.h>
#include <cuda_bf16.h>
#include <math.h>
#include <stdint.h>

#define BB 8
#define NN 512
#define KK 32
#define DD 128
#define HH 128
#define PP 8
#define NODES (BB*NN)

// Scratch (allocation-free rule: __device__ globals)
__device__ float g_pg[NODES*PP*3];
__device__ float g_R[NODES*9];
__device__ float g_t[NODES*3];
__device__ float g_s1[NODES*HH];        // static layer-1 pre-activation (incl bias)
__device__ float g_hs[NODES*HH];        // post-LN1 hidden state (fp32)
__device__ uint32_t g_hsb[NODES*64];    // post-LN1 hidden state (bf16 packed)
__device__ uint32_t g_sA[NODES*80];     // bf16-packed static A rows: hv(64)|pl(12)|pln(4) u32

// fragment-packed bf16 weights: [ng][ks][nth][lane] -> uint4(b0a,b1a,b0b,b1b)
__device__ uint4 g_w1e_b[2*16*4*32];   // Wm1 rows 128..383 (K=256, KS=16)
__device__ uint4 g_w1g_b[2*3*4*32];    // Wm1 rows 416..455 (K=40->48, KS=3)
__device__ uint4 g_ws_b[2*10*4*32];    // Wm1 static rows (K=160, KS=10; row map k<128?k:k+256)
__device__ uint4 g_w2_b[2*8*4*32];     // Wm2 (K=128, KS=8)
__device__ uint4 g_w3_b[2*8*4*32];     // Wm3
__device__ uint4 g_wd1_b[8*8*4*32];    // Wd1 (K=128, N=512: 8 n-groups, KS=8)
__device__ uint4 g_wd2_b[2*32*4*32];   // Wd2 (K=512, N=128: KS=32)

__device__ __forceinline__ uint32_t pkbf(float a, float b) {
    __nv_bfloat162 h = __floats2bfloat162_rn(a, b);
    return *reinterpret_cast<uint32_t*>(&h);
}

// ---------------------------------------------------------------------------
// weight packing helper (bf16 mma-fragment order)
// ---------------------------------------------------------------------------
__device__ __forceinline__ uint4 packb(const float* __restrict__ W, int ld,
                                       int Krows, int i, int KS)
{
    int lane = i & 31;
    int nth  = (i >> 5) & 3;
    int rest = i >> 7;
    int ks = rest % KS;
    int ng = rest / KS;
    int q = lane & 3;
    int gid = lane >> 2;
    int k0 = ks * 16;
    int na = ng*64 + nth*16 + gid;
    auto f = [&](int k, int n) -> float {
        return (k < Krows) ? W[(size_t)k*ld + n] : 0.f;
    };
    uint4 o;
    o.x = pkbf(f(k0+2*q,   na),   f(k0+2*q+1, na));
    o.y = pkbf(f(k0+2*q+8, na),   f(k0+2*q+9, na));
    o.z = pkbf(f(k0+2*q,   na+8), f(k0+2*q+1, na+8));
    o.w = pkbf(f(k0+2*q+8, na+8), f(k0+2*q+9, na+8));
    return o;
}

// static-row variant: K=160 rows of Wm1 with row map k<128 ? k : k+256
__device__ __forceinline__ uint4 packs(const float* __restrict__ Wm1, int i)
{
    int lane = i & 31;
    int nth  = (i >> 5) & 3;
    int rest = i >> 7;
    int ks = rest % 10;
    int ng = rest / 10;
    int q = lane & 3;
    int gid = lane >> 2;
    int k0 = ks * 16;
    int na = ng*64 + nth*16 + gid;
    auto f = [&](int k, int n) -> float {
        int r = (k < 128) ? k : k + 256;
        return Wm1[(size_t)r*128 + n];
    };
    uint4 o;
    o.x = pkbf(f(k0+2*q,   na),   f(k0+2*q+1, na));
    o.y = pkbf(f(k0+2*q+8, na),   f(k0+2*q+9, na));
    o.z = pkbf(f(k0+2*q,   na+8), f(k0+2*q+1, na+8));
    o.w = pkbf(f(k0+2*q+8, na+8), f(k0+2*q+9, na+8));
    return o;
}

// ---------------------------------------------------------------------------
// Kernel 1: blocks [0, NODES/NPB): frames + points + packed static A rows,
//           NPB nodes/CTA. blocks [NODES/NPB, +64): weight packing.
// ---------------------------------------------------------------------------
#define NPB 4
__global__ void node_prep_kernel(const float* __restrict__ hV_g,
                                 const float* __restrict__ X,
                                 const float* __restrict__ Wp,
                                 const float* __restrict__ bp,
                                 const float* __restrict__ Wm1,
                                 const float* __restrict__ Wm2,
                                 const float* __restrict__ Wm3,
                                 const float* __restrict__ Wd1,
                                 const float* __restrict__ Wd2)
{
    int t = threadIdx.x;
    if (blockIdx.x >= NODES/NPB) {
        int i = (blockIdx.x - NODES/NPB) * 128 + t;   // 0..8191
        if (i < 2*16*4*32) g_w1e_b[i] = packb(Wm1 + 128*128, 128, 256, i, 16);
        if (i < 2*8*4*32) {
            g_w2_b[i] = packb(Wm2, 128, 128, i, 8);
            g_w3_b[i] = packb(Wm3, 128, 128, i, 8);
        }
        if (i < 2*3*4*32)  g_w1g_b[i] = packb(Wm1 + 416*128, 128, 40, i, 3);
        if (i < 2*10*4*32) g_ws_b[i] = packs(Wm1, i);
        if (i < 8*8*4*32)  g_wd1_b[i] = packb(Wd1, 512, 128, i, 8);
        if (i < 2*32*4*32) g_wd2_b[i] = packb(Wd2, 128, 512, i, 32);
        return;
    }

    int node0 = blockIdx.x * NPB;
    __shared__ float hvS[NPB*128];
    __shared__ float plS[NPB*24];
    __shared__ float plnS[NPB*8];
    __shared__ float RnS[NPB*9];
    __shared__ float tnS[NPB*3];

    #pragma unroll
    for (int nn = 0; nn < NPB; ++nn)
        hvS[nn*128 + t] = hV_g[(size_t)(node0+nn)*DD + t];
    __syncthreads();

    if (t < NPB*24) {
        int nn = t / 24, j = t % 24;
        float acc = bp[j];
        #pragma unroll 8
        for (int d = 0; d < DD; ++d) acc += hvS[nn*128 + d] * Wp[d*24 + j];
        plS[nn*24 + j] = acc;
    } else if (t < NPB*24 + NPB) {
        int nn = t - NPB*24;
        const float* x = X + (size_t)(node0+nn)*9;
        float Xn0=x[0],Xn1=x[1],Xn2=x[2];
        float Xa0=x[3],Xa1=x[4],Xa2=x[5];
        float Xc0=x[6],Xc1=x[7],Xc2=x[8];
        float v10=Xc0-Xa0, v11=Xc1-Xa1, v12=Xc2-Xa2;
        float v20=Xn0-Xa0, v21=Xn1-Xa1, v22=Xn2-Xa2;
        float inv1 = rsqrtf(v10*v10+v11*v11+v12*v12+1e-8f);
        float e10=v10*inv1, e11=v11*inv1, e12=v12*inv1;
        float dp = e10*v20+e11*v21+e12*v22;
        float u20=v20-e10*dp, u21=v21-e11*dp, u22=v22-e12*dp;
        float inv2 = rsqrtf(u20*u20+u21*u21+u22*u22+1e-8f);
        float e20=u20*inv2, e21=u21*inv2, e22=u22*inv2;
        float e30=e11*e22-e12*e21;
        float e31=e12*e20-e10*e22;
        float e32=e10*e21-e11*e20;
        float* Rn = RnS + nn*9;
        Rn[0]=e10; Rn[1]=e20; Rn[2]=e30;
        Rn[3]=e11; Rn[4]=e21; Rn[5]=e31;
        Rn[6]=e12; Rn[7]=e22; Rn[8]=e32;
        tnS[nn*3+0]=Xa0*0.1f; tnS[nn*3+1]=Xa1*0.1f; tnS[nn*3+2]=Xa2*0.1f;
    }
    __syncthreads();

    if (t < NPB*8) {
        int nn = t >> 3, p = t & 7;
        float a=plS[nn*24+p*3+0], b=plS[nn*24+p*3+1], c=plS[nn*24+p*3+2];
        plnS[nn*8+p] = sqrtf(a*a+b*b+c*c + 1e-8f);
    }
    __syncthreads();

    if (t < NPB*24) {
        int nn = t / 24, j = t % 24;
        int p = j/3, i = j%3;
        const float* Rn = RnS + nn*9;
        float pg = tnS[nn*3+i] + Rn[i*3+0]*plS[nn*24+p*3+0]
                 + Rn[i*3+1]*plS[nn*24+p*3+1] + Rn[i*3+2]*plS[nn*24+p*3+2];
        g_pg[(size_t)(node0+nn)*24 + t] = pg;
    }
    if (t < NPB*9) g_R[(size_t)node0*9 + t] = RnS[t];
    if (t < NPB*3) g_t[(size_t)node0*3 + t] = tnS[t];

    for (int idx = t; idx < NPB*80; idx += 128) {
        int nn = idx / 80, c = idx % 80;
        uint32_t v;
        if (c < 64)      v = pkbf(hvS[nn*128 + 2*c],       hvS[nn*128 + 2*c + 1]);
        else if (c < 76) { int j = (c-64)*2; v = pkbf(plS[nn*24 + j], plS[nn*24 + j + 1]); }
        else             { int p = (c-76)*2; v = pkbf(plnS[nn*8 + p], plnS[nn*8 + p + 1]); }
        g_sA[(size_t)(node0+nn)*80 + c] = v;
    }
}

// ---------------------------------------------------------------------------
// bf16 m16n8k16 mma helpers
// ---------------------------------------------------------------------------
__device__ __forceinline__ void mma16816(float (&d)[4],
                                         uint32_t a0, uint32_t a1,
                                         uint32_t a2, uint32_t a3,
                                         uint32_t b0, uint32_t b1)
{
    asm volatile(
        "mma.sync.aligned.m16n8k16.row.col.f32.bf16.bf16.f32 "
        "{%0,%1,%2,%3},{%4,%5,%6,%7},{%8,%9},{%0,%1,%2,%3};"
        : "+f"(d[0]), "+f"(d[1]), "+f"(d[2]), "+f"(d[3])
        : "r"(a0), "r"(a1), "r"(a2), "r"(a3), "r"(b0), "r"(b1));
}

template<int KSTEPS>
__device__ __forceinline__ void mma_blk(float (*acc)[4],
                                        const uint32_t* r0, const uint32_t* r1,
                                        const uint4* __restrict__ frag)
{
    #pragma unroll
    for (int ks = 0; ks < KSTEPS; ++ks) {
        uint32_t a0 = r0[ks*8], a1 = r1[ks*8], a2 = r0[ks*8+4], a3 = r1[ks*8+4];
        const uint4* fb = frag + ks*128;
        #pragma unroll
        for (int nth = 0; nth < 4; ++nth) {
            uint4 b = fb[nth*32];
            mma16816(acc[2*nth],   a0, a1, a2, a3, b.x, b.y);
            mma16816(acc[2*nth+1], a0, a1, a2, a3, b.z, b.w);
        }
    }
}

// 2-mtile variant: warp covers 32 edges (rows r0/r1 and r2/r3) x 32 cols.
template<int KSTEPS>
__device__ __forceinline__ void mma_blk2(float (*acc)[4],
                                         const uint32_t* r0, const uint32_t* r1,
                                         const uint32_t* r2, const uint32_t* r3,
                                         const uint4* __restrict__ frag, int sub)
{
    #pragma unroll
    for (int ks = 0; ks < KSTEPS; ++ks) {
        uint32_t a0 = r0[ks*8], a1 = r1[ks*8], a2 = r0[ks*8+4], a3 = r1[ks*8+4];
        uint32_t c0 = r2[ks*8], c1 = r3[ks*8], c2 = r2[ks*8+4], c3 = r3[ks*8+4];
        const uint4* fb = frag + ks*128;
        uint4 b0 = fb[(sub*2+0)*32];
        uint4 b1 = fb[(sub*2+1)*32];
        mma16816(acc[0], a0,a1,a2,a3, b0.x, b0.y);
        mma16816(acc[1], a0,a1,a2,a3, b0.z, b0.w);
        mma16816(acc[2], a0,a1,a2,a3, b1.x, b1.y);
        mma16816(acc[3], a0,a1,a2,a3, b1.z, b1.w);
        mma16816(acc[4], c0,c1,c2,c3, b0.x, b0.y);
        mma16816(acc[5], c0,c1,c2,c3, b0.z, b0.w);
        mma16816(acc[6], c0,c1,c2,c3, b1.x, b1.y);
        mma16816(acc[7], c0,c1,c2,c3, b1.z, b1.w);
    }
}

__device__ __forceinline__ float warp_sum(float v) {
    #pragma unroll
    for (int o = 16; o; o >>= 1) v += __shfl_xor_sync(0xffffffffu, v, o);
    return v;
}

// ---------------------------------------------------------------------------
// Kernel 1b: s1 = staticA @ Ws + bm1 via bf16 MMA, 64 nodes/CTA (grid 64)
// ---------------------------------------------------------------------------
#define SAST 84
__global__ void __launch_bounds__(256, 2)
s1_kernel(const float* __restrict__ bm1)
{
    __shared__ uint32_t sA[64*SAST];

    int node0 = blockIdx.x * 64;
    int t = threadIdx.x;
    int w = t >> 5, lane = t & 31;
    int mh = w & 3, ng = w >> 2;
    int gid = lane >> 2, q = lane & 3;

    {
        const uint4* src = (const uint4*)(g_sA + (size_t)node0*80);
        #pragma unroll
        for (int i = t; i < 64*20; i += 256) {
            int node = i / 20, c = i % 20;
            *(uint4*)(sA + node*SAST + c*4) = src[i];
        }
    }
    __syncthreads();

    float acc[8][4];
    #pragma unroll
    for (int nt = 0; nt < 8; ++nt)
        #pragma unroll
        for (int i = 0; i < 4; ++i) acc[nt][i] = 0.f;

    const uint32_t* r0 = sA + (mh*16 + gid)*SAST + q;
    const uint32_t* r1 = r0 + 8*SAST;
    mma_blk<10>(acc, r0, r1, g_ws_b + ng*(10*128) + lane);

    int r0i = mh*16 + gid, r1i = r0i + 8;
    #pragma unroll
    for (int nt = 0; nt < 8; ++nt) {
        int cb = ng*64 + nt*8 + 2*q;
        float ba = bm1[cb], bb = bm1[cb+1];
        g_s1[(size_t)(node0+r0i)*HH + cb]     = acc[nt][0] + ba;
        g_s1[(size_t)(node0+r0i)*HH + cb + 1] = acc[nt][1] + bb;
        g_s1[(size_t)(node0+r1i)*HH + cb]     = acc[nt][2] + ba;
        g_s1[(size_t)(node0+r1i)*HH + cb + 1] = acc[nt][3] + bb;
    }
}

// msg_kernel smem layout (u32 units)
#define AST 68          // 64 data u32 (128 bf16) + 4 pad
#define GST 28          // 24 data u32 (48 bf16) + 4 pad
#define SM_BUFA  0      // 64*68 = 4352 : h_E -> relu(L1)
#define SM_BUFB  4352   // nbr_hV -> relu(L2)
#define SM_GEO   8704   // 64*28 = 1792
#define SM_HV    10496  // 256 (fp32)
#define SM_S1    10752  // 256
#define SM_RN    11008  // 24
#define SM_TN    11032  // 8
#define SM_PGN   11040  // 48
#define SM_MA    11088  // 64
#define SM_RED   11152  // 16
#define SM_PD    11168  // 256
#define SM_EIX   11424  // 64
#define SM_U32   11488
#define SMEM_BYTES (SM_U32*4)

// ---------------------------------------------------------------------------
// Kernel 2: 2 nodes per CTA, bf16 MMA message MLP, ends at LN1 -> g_hs/g_hsb.
// 8 warps: mh2 = w&1 (node / 32-edge group), ng4 = w>>1 (32-col group).
// ---------------------------------------------------------------------------
__global__ void __launch_bounds__(256, 4)
msg_kernel(const float* __restrict__ hV_g, const float* __restrict__ hE_g,
           const float* __restrict__ maskA_g,
           const float* __restrict__ bm2, const float* __restrict__ bm3,
           const float* __restrict__ g1, const float* __restrict__ be1,
           const int* __restrict__ Eidx,
           float* __restrict__ outE, long long availE)
{
    extern __shared__ float smf[];
    uint32_t* smu = (uint32_t*)smf;
    uint32_t* bufA = smu + SM_BUFA;
    uint32_t* bufB = smu + SM_BUFB;
    uint32_t* geoU = smu + SM_GEO;
    float* hv  = smf + SM_HV;
    float* s1  = smf + SM_S1;
    float* Rn  = smf + SM_RN;
    float* tn  = smf + SM_TN;
    float* pgn = smf + SM_PGN;
    float* mA  = smf + SM_MA;
    float* red = smf + SM_RED;
    float* pd  = smf + SM_PD;
    int*   eix = (int*)(smu + SM_EIX);

    int node0 = blockIdx.x * 2;
    int batch = node0 / NN;
    int t = threadIdx.x;
    int w = t >> 5, lane = t & 31;
    int mh2 = w & 1, ng4 = w >> 1;
    int gid = lane >> 2, q = lane & 3;

    hv[t] = hV_g[(size_t)node0*DD + t];
    s1[t] = g_s1[(size_t)node0*HH + t];
    if (t < 48) pgn[t] = g_pg[(size_t)node0*24 + t];
    else if (t < 66) Rn[t-48] = g_R[(size_t)node0*9 + (t-48)];
    else if (t < 72) tn[t-66] = g_t[(size_t)node0*3 + (t-66)];
    if (t >= 128 && t < 192) mA[t-128] = maskA_g[(size_t)node0*KK + (t-128)];
    else if (t >= 192) eix[t-192] = Eidx[(size_t)node0*KK + (t-192)];
    __syncthreads();

    // ============ fused staging: h_E->bufA (+passthrough), nbr->bufB, geo ==
    {
        long long ebase = (long long)node0 * KK * DD;
        const float4* src = (const float4*)(hE_g + ebase);
        float4* dst = (float4*)(outE + ebase);
        bool full = (ebase + 2*KK*DD) <= availE;
        #pragma unroll
        for (int i = 0; i < 8; ++i) {
            int f4 = t + i*256;          // 0..2047
            float4 v = src[f4];
            if (full || (ebase + (long long)f4*4 + 4) <= availE) dst[f4] = v;
            int e = f4 >> 5, cp = (f4 & 31) * 2;
            uint2 o;
            o.x = pkbf(v.x, v.y);
            o.y = pkbf(v.z, v.w);
            *(uint2*)(bufA + e*AST + cp) = o;
        }
    }
    // nbr_hV gather -> bufB
    #pragma unroll
    for (int ii = 0; ii < 8; ++ii) {
        int e = w + ii*8;
        int j = eix[e];
        const float4* src = (const float4*)(hV_g + (size_t)(batch*NN + j)*DD);
        float4 v = src[lane];
        uint2 o;
        o.x = pkbf(v.x, v.y);
        o.y = pkbf(v.z, v.w);
        *(uint2*)(bufB + e*AST + lane*2) = o;
    }
    // geometry rows
    #pragma unroll
    for (int ii = 0; ii < 8; ++ii) {
        int e = w + ii*8;
        if (lane < 8) {
            int p = lane;
            int nn = e >> 5;
            int j = eix[e];
            const float* qg = g_pg + (size_t)(batch*NN + j)*24 + p*3;
            float q0 = qg[0], q1 = qg[1], q2 = qg[2];
            const float* R = Rn + nn*9;
            float d0 = pgn[nn*24+p*3+0]-q0, d1 = pgn[nn*24+p*3+1]-q1, d2 = pgn[nn*24+p*3+2]-q2;
            float cc0 = q0 - tn[nn*3+0], cc1 = q1 - tn[nn*3+1], cc2 = q2 - tn[nn*3+2];
            float l0 = R[0]*cc0 + R[3]*cc1 + R[6]*cc2;
            float l1 = R[1]*cc0 + R[4]*cc1 + R[7]*cc2;
            float l2 = R[2]*cc0 + R[5]*cc1 + R[8]*cc2;
            __nv_bfloat16* row = (__nv_bfloat16*)(geoU + e*GST);
            row[p*3+0] = __float2bfloat16_rn(l0);
            row[p*3+1] = __float2bfloat16_rn(l1);
            row[p*3+2] = __float2bfloat16_rn(l2);
            row[24+p] = __float2bfloat16_rn(sqrtf(l0*l0+l1*l1+l2*l2 + 1e-8f));
            row[32+p] = __float2bfloat16_rn(sqrtf(d0*d0+d1*d1+d2*d2 + 1e-8f));
            if (p == 0) {
                uint32_t* ru = geoU + e*GST;
                ru[20] = 0u; ru[21] = 0u; ru[22] = 0u; ru[23] = 0u;
            }
        }
    }
    __syncthreads();

    int rowB = mh2*32 + gid;
    const uint32_t* a_r0 = bufA + rowB*AST + q;
    const uint32_t* a_r1 = a_r0 + 8*AST;
    const uint32_t* a_r2 = a_r0 + 16*AST;
    const uint32_t* a_r3 = a_r0 + 24*AST;
    const uint32_t* b_r0 = bufB + rowB*AST + q;
    const uint32_t* b_r1 = b_r0 + 8*AST;
    const uint32_t* b_r2 = b_r0 + 16*AST;
    const uint32_t* b_r3 = b_r0 + 24*AST;
    int ngp = ng4 >> 1, sub = ng4 & 1;

    // ============ layer 1: A (h_E) + B (nbr) + geo, back-to-back ============
    float acc[8][4];
    #pragma unroll
    for (int nt = 0; nt < 8; ++nt)
        #pragma unroll
        for (int i = 0; i < 4; ++i) acc[nt][i] = 0.f;

    mma_blk2<8>(acc, a_r0, a_r1, a_r2, a_r3, g_w1e_b + ngp*(16*128) + lane, sub);
    mma_blk2<8>(acc, b_r0, b_r1, b_r2, b_r3, g_w1e_b + ngp*(16*128) + 8*128 + lane, sub);
    {
        const uint32_t* g_r0 = geoU + rowB*GST + q;
        mma_blk2<3>(acc, g_r0, g_r0 + 8*GST, g_r0 + 16*GST, g_r0 + 24*GST,
                    g_w1g_b + ngp*(3*128) + lane, sub);
    }
    __syncthreads();   // all reads of bufA / bufB complete

    // add static part + relu, store bf16 to bufA (h_E dead)
    {
        const float* s1n = s1 + mh2*128;
        #pragma unroll
        for (int nt = 0; nt < 4; ++nt) {
            int cb = ng4*32 + nt*8 + 2*q;
            float sa = s1n[cb], sb = s1n[cb+1];
            int cp = cb >> 1;
            bufA[rowB*AST + cp] =
                pkbf(fmaxf(acc[nt][0] + sa, 0.f), fmaxf(acc[nt][1] + sb, 0.f));
            bufA[(rowB+8)*AST + cp] =
                pkbf(fmaxf(acc[nt][2] + sa, 0.f), fmaxf(acc[nt][3] + sb, 0.f));
            bufA[(rowB+16)*AST + cp] =
                pkbf(fmaxf(acc[4+nt][0] + sa, 0.f), fmaxf(acc[4+nt][1] + sb, 0.f));
            bufA[(rowB+24)*AST + cp] =
                pkbf(fmaxf(acc[4+nt][2] + sa, 0.f), fmaxf(acc[4+nt][3] + sb, 0.f));
        }
    }
    __syncthreads();

    // ============ layer 2 (reads bufA, writes bufB) ========================
    #pragma unroll
    for (int nt = 0; nt < 8; ++nt)
        #pragma unroll
        for (int i = 0; i < 4; ++i) acc[nt][i] = 0.f;
    mma_blk2<8>(acc, a_r0, a_r1, a_r2, a_r3, g_w2_b + ngp*(8*128) + lane, sub);
    __syncthreads();   // scheduling fence: keeps bufB store after all L2 reads
    {
        #pragma unroll
        for (int nt = 0; nt < 4; ++nt) {
            int cb = ng4*32 + nt*8 + 2*q;
            float ba = bm2[cb], bb = bm2[cb+1];
            int cp = cb >> 1;
            bufB[rowB*AST + cp] =
                pkbf(fmaxf(acc[nt][0] + ba, 0.f), fmaxf(acc[nt][1] + bb, 0.f));
            bufB[(rowB+8)*AST + cp] =
                pkbf(fmaxf(acc[nt][2] + ba, 0.f), fmaxf(acc[nt][3] + bb, 0.f));
            bufB[(rowB+16)*AST + cp] =
                pkbf(fmaxf(acc[4+nt][0] + ba, 0.f), fmaxf(acc[4+nt][1] + bb, 0.f));
            bufB[(rowB+24)*AST + cp] =
                pkbf(fmaxf(acc[4+nt][2] + ba, 0.f), fmaxf(acc[4+nt][3] + bb, 0.f));
        }
    }
    __syncthreads();

    // ============ layer 3 (reads bufB) + masked full per-warp mean =========
    #pragma unroll
    for (int nt = 0; nt < 8; ++nt)
        #pragma unroll
        for (int i = 0; i < 4; ++i) acc[nt][i] = 0.f;
    mma_blk2<8>(acc, b_r0, b_r1, b_r2, b_r3, g_w3_b + ngp*(8*128) + lane, sub);
    {
        float mk0 = mA[mh2*32 + gid];
        float mk1 = mA[mh2*32 + gid + 8];
        float mk2 = mA[mh2*32 + gid + 16];
        float mk3 = mA[mh2*32 + gid + 24];
        #pragma unroll
        for (int nt = 0; nt < 4; ++nt) {
            int cb = ng4*32 + nt*8 + 2*q;
            float ba = bm3[cb], bb = bm3[cb+1];
            float ve = (acc[nt][0] + ba)*mk0 + (acc[nt][2] + ba)*mk1
                     + (acc[4+nt][0] + ba)*mk2 + (acc[4+nt][2] + ba)*mk3;
            float vo = (acc[nt][1] + bb)*mk0 + (acc[nt][3] + bb)*mk1
                     + (acc[4+nt][1] + bb)*mk2 + (acc[4+nt][3] + bb)*mk3;
            #pragma unroll
            for (int o = 4; o <= 16; o <<= 1) {
                ve += __shfl_xor_sync(0xffffffffu, ve, o);
                vo += __shfl_xor_sync(0xffffffffu, vo, o);
            }
            if (gid == 0) {
                pd[mh2*128 + cb] = ve;
                pd[mh2*128 + cb + 1] = vo;
            }
        }
    }
    __syncthreads();

    // ---------------- LN1 for both nodes -> g_hs + g_hsb ----------------
    int nodeL = t >> 7, c = t & 127;
    float x, dx;
    {
        float nm = pd[nodeL*128 + c] * (1.0f/KK);
        x = hv[nodeL*128 + c] + nm;
        float sA = warp_sum(x);
        if (!lane) red[w] = sA;
    }
    __syncthreads();
    {
        float mu = (red[nodeL*4+0]+red[nodeL*4+1]+red[nodeL*4+2]+red[nodeL*4+3]) * (1.0f/HH);
        dx = x - mu;
        float sB = warp_sum(dx*dx);
        __syncwarp();
        if (!lane) red[8+w] = sB;
    }
    __syncthreads();
    {
        float var = (red[8+nodeL*4]+red[9+nodeL*4]+red[10+nodeL*4]+red[11+nodeL*4]) * (1.0f/HH);
        float xn = dx * rsqrtf(var + 1e-5f) * g1[c] + be1[c];
        g_hs[(size_t)(node0+nodeL)*HH + c] = xn;
        float xo = __shfl_xor_sync(0xffffffffu, xn, 1);
        if (!(c & 1))
            g_hsb[(size_t)(node0+nodeL)*64 + (c >> 1)] = pkbf(xn, xo);
    }
}

// dense kernel smem layout (u32 units), 16 nodes / CTA
#define D1ST 260       // 256 data u32 (512 bf16) + 4 pad
#define DM_HSB 0       // 16*68 = 1088
#define DM_D1B 1088    // 16*260 = 4160
#define DM_HSF 5248    // 2048 (fp32)
#define DM_X2  7296    // 2048 (fp32)
#define DM_U32 9344
#define DSMEM_BYTES (DM_U32*4)

// ---------------------------------------------------------------------------
// Kernel 3: dense FFN + LN2 + mask, 16 nodes per CTA (grid 256), bf16 MMA.
// ---------------------------------------------------------------------------
__global__ void __launch_bounds__(256, 2)
dense_kernel(const float* __restrict__ maskV_g,
             const float* __restrict__ bd1, const float* __restrict__ bd2,
             const float* __restrict__ g2, const float* __restrict__ be2,
             float* __restrict__ out)
{
    extern __shared__ float smf[];
    uint32_t* smu = (uint32_t*)smf;
    uint32_t* hsb = smu + DM_HSB;
    uint32_t* d1b = smu + DM_D1B;
    float* hsf = smf + DM_HSF;
    float* x2s = smf + DM_X2;

    int node0 = blockIdx.x * 16;
    int t = threadIdx.x;
    int w = t >> 5, lane = t & 31;
    int gid = lane >> 2, q = lane & 3;

    // stage hs: fp32 copy (residual) + packed bf16 copy
    {
        const float2* src = (const float2*)(g_hs + (size_t)node0*HH);
        #pragma unroll
        for (int i = t; i < 1024; i += 256) {
            float2 v = src[i];
            int row = i >> 6, cp = i & 63;
            hsf[row*128 + cp*2]     = v.x;
            hsf[row*128 + cp*2 + 1] = v.y;
        }
        const uint32_t* srcb = g_hsb + (size_t)node0*64;
        #pragma unroll
        for (int i = t; i < 1024; i += 256) {
            int row = i >> 6, cp = i & 63;
            hsb[row*AST + cp] = srcb[i];
        }
    }
    __syncthreads();

    const uint32_t* a_r0 = hsb + gid*AST + q;
    const uint32_t* a_r1 = a_r0 + 8*AST;

    // ---------------- dense1: 128 -> 512, relu, bf16 out ----------------
    {
        float acc[8][4];
        #pragma unroll
        for (int nt = 0; nt < 8; ++nt)
            #pragma unroll
            for (int i = 0; i < 4; ++i) acc[nt][i] = 0.f;
        mma_blk<8>(acc, a_r0, a_r1, g_wd1_b + w*(8*128) + lane);
        #pragma unroll
        for (int nt = 0; nt < 8; ++nt) {
            int cb = w*64 + nt*8 + 2*q;
            float ba = bd1[cb], bb = bd1[cb+1];
            d1b[gid*D1ST + (cb>>1)] =
                pkbf(fmaxf(acc[nt][0] + ba, 0.f), fmaxf(acc[nt][1] + bb, 0.f));
            d1b[(gid+8)*D1ST + (cb>>1)] =
                pkbf(fmaxf(acc[nt][2] + ba, 0.f), fmaxf(acc[nt][3] + bb, 0.f));
        }
    }
    __syncthreads();

    // ---------------- dense2: 512 -> 128, + bd2 + residual ----------------
    {
        float acc[2][4];
        #pragma unroll
        for (int nt = 0; nt < 2; ++nt)
            #pragma unroll
            for (int i = 0; i < 4; ++i) acc[nt][i] = 0.f;
        const uint32_t* d_r0 = d1b + gid*D1ST + q;
        const uint32_t* d_r1 = d_r0 + 8*D1ST;
        int ng2 = w >> 2, nth2 = w & 3;
        const uint4* frag = g_wd2_b + ng2*(32*128) + lane;
        #pragma unroll 8
        for (int ks = 0; ks < 32; ++ks) {
            uint32_t a0 = d_r0[ks*8], a1 = d_r1[ks*8], a2 = d_r0[ks*8+4], a3 = d_r1[ks*8+4];
            uint4 b = frag[ks*128 + nth2*32];
            mma16816(acc[0], a0, a1, a2, a3, b.x, b.y);
            mma16816(acc[1], a0, a1, a2, a3, b.z, b.w);
        }
        int r0 = gid, r1 = gid + 8;
        #pragma unroll
        for (int nt = 0; nt < 2; ++nt) {
            int cb = ng2*64 + nth2*16 + nt*8 + 2*q;
            float ba = bd2[cb], bb = bd2[cb+1];
            x2s[r0*128 + cb]     = acc[nt][0] + ba + hsf[r0*128 + cb];
            x2s[r0*128 + cb + 1] = acc[nt][1] + bb + hsf[r0*128 + cb + 1];
            x2s[r1*128 + cb]     = acc[nt][2] + ba + hsf[r1*128 + cb];
            x2s[r1*128 + cb + 1] = acc[nt][3] + bb + hsf[r1*128 + cb + 1];
        }
    }
    __syncthreads();

    // ---------------- LN2 + mask: warp w handles nodes w*2, w*2+1 ----------
    #pragma unroll
    for (int nn = 0; nn < 2; ++nn) {
        int row = w*2 + nn;
        float v0 = x2s[row*128 + lane];
        float v1 = x2s[row*128 + lane + 32];
        float v2 = x2s[row*128 + lane + 64];
        float v3 = x2s[row*128 + lane + 96];
        float mu = warp_sum(v0+v1+v2+v3) * (1.0f/HH);
        float d0 = v0-mu, d1 = v1-mu, d2 = v2-mu, d3 = v3-mu;
        float var = warp_sum(d0*d0+d1*d1+d2*d2+d3*d3) * (1.0f/HH);
        float rs = rsqrtf(var + 1e-5f);
        float mk = maskV_g[node0 + row];
        float* o = out + (size_t)(node0 + row)*HH;
        o[lane]      = (d0*rs*g2[lane]      + be2[lane])      * mk;
        o[lane + 32] = (d1*rs*g2[lane + 32] + be2[lane + 32]) * mk;
        o[lane + 64] = (d2*rs*g2[lane + 64] + be2[lane + 64]) * mk;
        o[lane + 96] = (d3*rs*g2[lane + 96] + be2[lane + 96]) * mk;
    }
}

// ---------------------------------------------------------------------------
extern "C" void kernel_launch(void* const* d_in, const int* in_sizes, int n_in,
                              void* d_out, int out_size)
{
    const float* hV    = (const float*)d_in[0];
    const float* hE    = (const float*)d_in[1];
    const float* X     = (const float*)d_in[2];
    const float* maskV = (const float*)d_in[3];
    const float* maskA = (const float*)d_in[4];
    const float* Wp    = (const float*)d_in[5];
    const float* bp    = (const float*)d_in[6];
    const float* Wm1   = (const float*)d_in[7];
    const float* bm1   = (const float*)d_in[8];
    const float* Wm2   = (const float*)d_in[9];
    const float* bm2   = (const float*)d_in[10];
    const float* Wm3   = (const float*)d_in[11];
    const float* bm3   = (const float*)d_in[12];
    const float* g1    = (const float*)d_in[13];
    const float* be1   = (const float*)d_in[14];
    const float* Wd1   = (const float*)d_in[15];
    const float* bd1   = (const float*)d_in[16];
    const float* Wd2   = (const float*)d_in[17];
    const float* bd2   = (const float*)d_in[18];
    const float* g2    = (const float*)d_in[19];
    const float* be2   = (const float*)d_in[20];
    const int*   Eidx  = (const int*)d_in[21];
    float* out = (float*)d_out;

    cudaFuncSetAttribute(msg_kernel, cudaFuncAttributeMaxDynamicSharedMemorySize, SMEM_BYTES);
    cudaFuncSetAttribute(dense_kernel, cudaFuncAttributeMaxDynamicSharedMemorySize, DSMEM_BYTES);

    long long hcount = (long long)NODES * HH;
    long long availE = (long long)out_size - hcount;
    if (availE < 0) availE = 0;
    long long emax = (long long)BB*NN*KK*DD;
    if (availE > emax) availE = emax;

    node_prep_kernel<<<NODES/NPB + 64, 128>>>(hV, X, Wp, bp, Wm1,
                                              Wm2, Wm3, Wd1, Wd2);
    s1_kernel<<<NODES/64, 256>>>(bm1);
    msg_kernel<<<NODES/2, 256, SMEM_BYTES>>>(hV, hE, maskA, bm2, bm3,
                                             g1, be1, Eidx,
                                             out + hcount, availE);
    dense_kernel<<<NODES/16, 256, DSMEM_BYTES>>>(maskV, bd1, bd2, g2, be2, out);
}